// round 5
// baseline (speedup 1.0000x reference)
#include <cuda_runtime.h>
#include <math.h>

// Problem constants (fixed by the dataset)
#define NB    4
#define C_IN  256
#define HH    64
#define WW    64
#define O_OUT 256
// M = NB*HH*WW = 16384 positions, K = C_IN*9 = 2304, N = O_OUT = 256

// Scratch (allocation-free rule: __device__ globals)
__device__ float g_xT[(size_t)NB * HH * WW * C_IN];  // [n][h][w][c]  (channels contiguous)
__device__ float g_wT[9 * C_IN * O_OUT];             // [k][c][o]     (o contiguous)

// ---------------------------------------------------------------------------
// Transpose x: [N,C,H,W] -> [N,H,W,C] with a 32x32 smem tile (coalesced both ways)
// grid: (16, N*H), block: 256  (tx=0..31 over w/c, ty=0..7)
// ---------------------------------------------------------------------------
__global__ void transpose_x_kernel(const float* __restrict__ x) {
    __shared__ float tile[32][33];
    const int nh = blockIdx.y;                 // n*64 + h
    const int c0 = (blockIdx.x >> 1) << 5;     // 0..224
    const int w0 = (blockIdx.x & 1) << 5;      // 0 or 32
    const int tx = threadIdx.x & 31;
    const int ty = threadIdx.x >> 5;           // 0..7
    const int n  = nh >> 6;
    const int h  = nh & 63;

    const float* xp = x + ((size_t)n * C_IN + c0) * (HH * WW) + h * WW + w0;
#pragma unroll
    for (int i = 0; i < 32; i += 8)
        tile[ty + i][tx] = xp[(size_t)(ty + i) * (HH * WW) + tx];
    __syncthreads();
    float* op = g_xT + ((size_t)nh * WW + w0) * C_IN + c0;
#pragma unroll
    for (int i = 0; i < 32; i += 8)
        op[(size_t)(ty + i) * C_IN + tx] = tile[tx][ty + i];
}

// ---------------------------------------------------------------------------
// Transpose weight: [O,C,3,3] -> [k][c][o]
// ---------------------------------------------------------------------------
__global__ void transpose_w_kernel(const float* __restrict__ w) {
    int idx = blockIdx.x * 256 + threadIdx.x;  // linear in wT
    if (idx >= 9 * C_IN * O_OUT) return;
    int o = idx & 255;
    int c = (idx >> 8) & 255;
    int k = idx >> 16;
    g_wT[idx] = w[(o * C_IN + c) * 9 + k];
}

// ---------------------------------------------------------------------------
// Fused bilinear-im2col + SGEMM.
// One block = one (n,h) row: 64 positions (w=0..63) x all 256 output channels.
// 256 threads, each computes an 8(pos) x 8(out) register tile.
// K loop: 9 taps x 16 chunks of 16 channels.
// ---------------------------------------------------------------------------
__global__ __launch_bounds__(256, 2)
void deform_gemm_kernel(const float* __restrict__ offset, float* __restrict__ out) {
    __shared__ int   s_addr[4][576];   // per (corner, k*64+w): clamped base offset into g_xT
    __shared__ float s_wgt[4][576];    // per corner: bilinear weight * validity
    __shared__ float As[16][64];       // [cc][pos]
    __shared__ float Bs[16][256];      // [cc][o]

    const int t   = threadIdx.x;
    const int blk = blockIdx.x;        // 0..255
    const int n   = blk >> 6;
    const int h   = blk & 63;
    const int hw0 = h * 64;

    // ---- Precompute bilinear descriptors: 576 = 9 taps * 64 positions ----
    for (int e = t; e < 576; e += 256) {
        const int k  = e >> 6;        // tap 0..8
        const int w  = e & 63;        // position within row
        const int hw = hw0 + w;
        const float* ob = offset + ((n * 4096 + hw) * 18 + 2 * k);
        const float dy = ob[0];
        const float dx = ob[1];
        const float py = (float)(h + (k / 3) - 1) + dy;
        const float px = (float)(w + (k % 3) - 1) + dx;
        const float fy = floorf(py), fx = floorf(px);
        const float wy = py - fy,    wx = px - fx;
        const int iy0 = (int)fy, ix0 = (int)fx;
        const float cw0 = (1.f - wy) * (1.f - wx);
        const float cw1 = (1.f - wy) * wx;
        const float cw2 = wy * (1.f - wx);
        const float cw3 = wy * wx;
        const float cw[4] = {cw0, cw1, cw2, cw3};
#pragma unroll
        for (int q = 0; q < 4; q++) {
            const int iy = iy0 + (q >> 1);
            const int ix = ix0 + (q & 1);
            const bool valid = (iy >= 0) && (iy < HH) && (ix >= 0) && (ix < WW);
            const int iyc = min(max(iy, 0), HH - 1);
            const int ixc = min(max(ix, 0), WW - 1);
            s_addr[q][e] = ((n * HH + iyc) * WW + ixc) * C_IN;
            s_wgt[q][e]  = valid ? cw[q] : 0.f;
        }
    }
    __syncthreads();

    float acc[8][8];
#pragma unroll
    for (int i = 0; i < 8; i++)
#pragma unroll
        for (int j = 0; j < 8; j++) acc[i][j] = 0.f;

    const int tm = t & 7;    // position-group  -> pos = tm*8 + i
    const int tn = t >> 3;   // output-group    -> o   = tn*8 + j
    const int pg = t & 63;   // A-gen: this thread's position
    const int cg = t >> 6;   // A-gen: channel sub-group 0..3

    for (int k = 0; k < 9; k++) {
        // hoist this thread's sampling descriptor for tap k
        const int e = k * 64 + pg;
        const int   a0 = s_addr[0][e], a1 = s_addr[1][e], a2 = s_addr[2][e], a3 = s_addr[3][e];
        const float q0 = s_wgt[0][e],  q1 = s_wgt[1][e],  q2 = s_wgt[2][e],  q3 = s_wgt[3][e];
        const float* wkb = g_wT + k * (C_IN * O_OUT);

        for (int c0 = 0; c0 < C_IN; c0 += 16) {
            __syncthreads();   // previous chunk's As/Bs reads done

            // ---- Load B tile: 16 x 256 floats = 1024 float4, 4 per thread ----
#pragma unroll
            for (int j = 0; j < 4; j++) {
                const int f  = t + j * 256;
                const int cc = f >> 6;          // 64 float4 per row
                const int o4 = f & 63;
                const float4 v = *(const float4*)(wkb + (c0 + cc) * O_OUT + o4 * 4);
                *(float4*)(&Bs[cc][o4 * 4]) = v;
            }

            // ---- Generate A tile: bilinear sample 4 channels for position pg ----
            {
                const int cofs = c0 + cg * 4;
                const float4 v0 = *(const float4*)(g_xT + a0 + cofs);
                const float4 v1 = *(const float4*)(g_xT + a1 + cofs);
                const float4 v2 = *(const float4*)(g_xT + a2 + cofs);
                const float4 v3 = *(const float4*)(g_xT + a3 + cofs);
                As[cg * 4 + 0][pg] = q0 * v0.x + q1 * v1.x + q2 * v2.x + q3 * v3.x;
                As[cg * 4 + 1][pg] = q0 * v0.y + q1 * v1.y + q2 * v2.y + q3 * v3.y;
                As[cg * 4 + 2][pg] = q0 * v0.z + q1 * v1.z + q2 * v2.z + q3 * v3.z;
                As[cg * 4 + 3][pg] = q0 * v0.w + q1 * v1.w + q2 * v2.w + q3 * v3.w;
            }
            __syncthreads();

            // ---- Register-tiled FFMA GEMM over this K-chunk ----
#pragma unroll
            for (int cc = 0; cc < 16; cc++) {
                const float4 A0 = *(const float4*)(&As[cc][tm * 8]);
                const float4 A1 = *(const float4*)(&As[cc][tm * 8 + 4]);
                const float4 B0 = *(const float4*)(&Bs[cc][tn * 8]);
                const float4 B1 = *(const float4*)(&Bs[cc][tn * 8 + 4]);
                const float a[8] = {A0.x, A0.y, A0.z, A0.w, A1.x, A1.y, A1.z, A1.w};
                const float b[8] = {B0.x, B0.y, B0.z, B0.w, B1.x, B1.y, B1.z, B1.w};
#pragma unroll
                for (int i = 0; i < 8; i++)
#pragma unroll
                    for (int j = 0; j < 8; j++)
                        acc[i][j] += a[i] * b[j];
            }
        }
    }

    // ---- Write out[n][o][h][w]: 8 consecutive w per float4 pair ----
    float* obase = out + (((size_t)n * O_OUT) << 12) + hw0 + tm * 8;
#pragma unroll
    for (int j = 0; j < 8; j++) {
        const int o = tn * 8 + j;
        float4 v0 = make_float4(acc[0][j], acc[1][j], acc[2][j], acc[3][j]);
        float4 v1 = make_float4(acc[4][j], acc[5][j], acc[6][j], acc[7][j]);
        *(float4*)(obase + ((size_t)o << 12))     = v0;
        *(float4*)(obase + ((size_t)o << 12) + 4) = v1;
    }
}

// ---------------------------------------------------------------------------
extern "C" void kernel_launch(void* const* d_in, const int* in_sizes, int n_in,
                              void* d_out, int out_size) {
    (void)out_size;
    // Identify inputs by element count (all distinct), robust to ordering.
    const float* x = nullptr;
    const float* offset = nullptr;
    const float* weight = nullptr;
    for (int i = 0; i < n_in; i++) {
        const int sz = in_sizes[i];
        if (sz == NB * C_IN * HH * WW)        x = (const float*)d_in[i];        // 4194304
        else if (sz == NB * HH * WW * 18)     offset = (const float*)d_in[i];   // 294912
        else if (sz == O_OUT * C_IN * 9)      weight = (const float*)d_in[i];   // 589824
    }
    float* out = (float*)d_out;

    transpose_x_kernel<<<dim3(16, NB * HH), 256>>>(x);
    transpose_w_kernel<<<(9 * C_IN * O_OUT + 255) / 256, 256>>>(weight);
    deform_gemm_kernel<<<NB * HH, 256>>>(offset, out);
}

// round 7
// speedup vs baseline: 1.9098x; 1.9098x over previous
#include <cuda_runtime.h>
#include <cuda_bf16.h>
#include <math.h>
#include <stdint.h>

// Problem constants
#define NB    4
#define HH    64
#define WW    64
#define C_IN  256
#define O_OUT 256
#define NCHUNK 36            // 9 taps * 4 channel-blocks of 64
// GEMM: M=16384 (positions), N=256 (outputs), K=2304 (tap-major)

// B tile per chunk: [256 o][64 c] bf16, rows padded to 72 bf16 = 144B.
// hi tile 256*144 = 36864 B, lo tile same; 73728 B per chunk.
#define BROW    144
#define BTILE   36864
#define BCHUNK  73728

// Scratch (__device__ globals per allocation-free rule)
__device__ float g_xT[(size_t)NB * HH * WW * C_IN];                 // [n][h][w][c]
__device__ __align__(128) unsigned char g_wB[(size_t)NCHUNK * BCHUNK];

// ---------------- PTX helpers (non-'a' features only) ----------------
__device__ __forceinline__ uint32_t smem_u32(const void* p) {
    uint32_t a;
    asm("{ .reg .u64 t; cvta.to.shared.u64 t, %1; cvt.u32.u64 %0, t; }" : "=r"(a) : "l"(p));
    return a;
}
__device__ __forceinline__ void ldsm4(uint32_t* r, uint32_t addr) {
    asm volatile("ldmatrix.sync.aligned.m8n8.x4.shared.b16 {%0,%1,%2,%3}, [%4];"
        : "=r"(r[0]), "=r"(r[1]), "=r"(r[2]), "=r"(r[3]) : "r"(addr));
}
__device__ __forceinline__ void cpasync16(uint32_t dst, const void* src) {
    asm volatile("cp.async.cg.shared.global [%0], [%1], 16;" :: "r"(dst), "l"(src) : "memory");
}
__device__ __forceinline__ void sts128(uint32_t addr, uint32_t a, uint32_t b, uint32_t c, uint32_t d) {
    asm volatile("st.shared.v4.b32 [%0], {%1, %2, %3, %4};" :: "r"(addr), "r"(a), "r"(b), "r"(c), "r"(d) : "memory");
}
__device__ __forceinline__ uint32_t packbf(float lo, float hi) {
    uint32_t r; asm("cvt.rn.bf16x2.f32 %0, %1, %2;" : "=r"(r) : "f"(hi), "f"(lo)); return r;  // low16 = lo
}
// 16 warp-MMAs: full 32(M) x 64(N) warp tile, one k16 step
__device__ __forceinline__ void mma_all(float (&acc)[2][8][4], const uint32_t* a, const uint32_t* b) {
#pragma unroll
    for (int mt = 0; mt < 2; mt++)
#pragma unroll
        for (int nn = 0; nn < 8; nn++) {
            const uint32_t* bb = b + (nn >> 1) * 4 + (nn & 1) * 2;
            asm volatile("mma.sync.aligned.m16n8k16.row.col.f32.bf16.bf16.f32 "
                "{%0,%1,%2,%3}, {%4,%5,%6,%7}, {%8,%9}, {%0,%1,%2,%3};"
                : "+f"(acc[mt][nn][0]), "+f"(acc[mt][nn][1]), "+f"(acc[mt][nn][2]), "+f"(acc[mt][nn][3])
                : "r"(a[mt * 4]), "r"(a[mt * 4 + 1]), "r"(a[mt * 4 + 2]), "r"(a[mt * 4 + 3]),
                  "r"(bb[0]), "r"(bb[1]));
        }
}

// -------- smem layout (dynamic) --------
// A tile: [128 m][64 c] bf16, rows padded to 144B. hi 18432 + lo 18432.
#define SM_ADDR   64                      // int[4][128]
#define SM_WGT    (64 + 2048)             // float[4][128]
#define SM_A      4224                    // hi; lo at +18432
#define ATILE     18432
#define SM_B      41088                   // stage s at + s*BCHUNK
#define SMEM_BYTES (41088 + 2 * BCHUNK)   // 188544

// ---------------------------------------------------------------------------
// x: [N,C,H,W] -> [N,H,W,C]
// ---------------------------------------------------------------------------
__global__ void transpose_x_kernel(const float* __restrict__ x) {
    __shared__ float tile[32][33];
    const int nh = blockIdx.y;
    const int c0 = (blockIdx.x >> 1) << 5;
    const int w0 = (blockIdx.x & 1) << 5;
    const int tx = threadIdx.x & 31;
    const int ty = threadIdx.x >> 5;
    const int n  = nh >> 6;
    const int h  = nh & 63;

    const float* xp = x + ((size_t)n * C_IN + c0) * (HH * WW) + h * WW + w0;
#pragma unroll
    for (int i = 0; i < 32; i += 8)
        tile[ty + i][tx] = xp[(size_t)(ty + i) * (HH * WW) + tx];
    __syncthreads();
    float* op = g_xT + ((size_t)nh * WW + w0) * C_IN + c0;
#pragma unroll
    for (int i = 0; i < 32; i += 8)
        op[(size_t)(ty + i) * C_IN + tx] = tile[tx][ty + i];
}

// ---------------------------------------------------------------------------
// weight [O,C,3,3] fp32 -> bf16 hi/lo, padded-row (144B) B tiles per chunk
// ---------------------------------------------------------------------------
__global__ void prep_w_kernel(const float* __restrict__ w) {
    int idx = blockIdx.x * 256 + threadIdx.x;          // 0 .. 36*8192-1
    if (idx >= NCHUNK * 8192) return;
    const int chunk = idx >> 13;
    const int r  = idx & 8191;
    const int o  = r >> 5;          // 0..255
    const int j2 = r & 31;          // bf16-pair index within 64-ch row
    const int tap = chunk >> 2, cb = chunk & 3;
    const int c = cb * 64 + 2 * j2;
    const float v0 = w[(o * C_IN + c) * 9 + tap];
    const float v1 = w[(o * C_IN + c + 1) * 9 + tap];
    const uint32_t hi = packbf(v0, v1);
    const float h0 = __uint_as_float(hi << 16);
    const float h1 = __uint_as_float(hi & 0xFFFF0000u);
    const uint32_t lo = packbf(v0 - h0, v1 - h1);
    unsigned char* base = g_wB + (size_t)chunk * BCHUNK + (size_t)o * BROW + j2 * 4;
    *(uint32_t*)(base)         = hi;
    *(uint32_t*)(base + BTILE) = lo;
}

// ---------------------------------------------------------------------------
// Fused bilinear-im2col + bf16-split mma.sync GEMM.
// grid = 128 CTAs (4 n x 32 tiles of 128 positions), 512 threads, 1 CTA/SM.
// Warp layout: 16 warps = 4(M blocks of 32) x 4(N blocks of 64).
// ---------------------------------------------------------------------------
__global__ __launch_bounds__(512, 1)
void deform_mma_kernel(const float* __restrict__ offset, float* __restrict__ out) {
    extern __shared__ char smem[];
    const uint32_t sb = smem_u32(smem);
    const int t    = threadIdx.x;
    const int blk  = blockIdx.x;           // 0..127
    const int nb   = blk >> 5;
    const int hwb  = (blk & 31) * 128;
    const int warp = t >> 5, lane = t & 31;
    const int wm = warp & 3, wn = warp >> 2;

    int*   s_addr = (int*)(smem + SM_ADDR);
    float* s_wgt  = (float*)(smem + SM_WGT);

    // Prefetch B chunk 0 into stage 0
    {
        const uint32_t dst = sb + SM_B;
#pragma unroll
        for (int i = 0; i < 9; i++) {
            const int off = (t + i * 512) * 16;
            cpasync16(dst + off, g_wB + off);
        }
        asm volatile("cp.async.commit_group;" ::: "memory");
    }

    float acc[2][8][4];
#pragma unroll
    for (int mt = 0; mt < 2; mt++)
#pragma unroll
        for (int nn = 0; nn < 8; nn++)
#pragma unroll
            for (int q = 0; q < 4; q++) acc[mt][nn][q] = 0.f;

    // per-thread constant addressing
    const int pos = t & 127;        // A-gen: position
    const int q4  = t >> 7;         // A-gen: 16-channel group (0..3)
    const uint32_t aGen  = sb + SM_A + pos * BROW + q4 * 32;
    const uint32_t aBase = sb + SM_A + (wm * 32 + (lane & 15)) * BROW + ((lane >> 4) << 4);
    const uint32_t bRowO = (uint32_t)(wn * 64 + (lane & 7) + ((lane >> 4) << 3)) * BROW
                         + (((lane >> 3) & 1) << 4);

    for (int chunk = 0; chunk < NCHUNK; chunk++) {
        const int s   = chunk & 1;
        const int tap = chunk >> 2;
        const int cb  = chunk & 3;

        __syncthreads();   // prior chunk's A/B readers done

        // prefetch next B chunk
        if (chunk + 1 < NCHUNK) {
            const uint32_t dst = sb + SM_B + (uint32_t)((chunk + 1) & 1) * BCHUNK;
            const unsigned char* src = g_wB + (size_t)(chunk + 1) * BCHUNK;
#pragma unroll
            for (int i = 0; i < 9; i++) {
                const int off = (t + i * 512) * 16;
                cpasync16(dst + off, src + off);
            }
            asm volatile("cp.async.commit_group;" ::: "memory");
        }

        // bilinear descriptors, once per tap
        if (cb == 0) {
            if (t < 128) {
                const int p  = t;
                const int hw = hwb + p;
                const int h  = hw >> 6, w = hw & 63;
                const float2 dydx = *(const float2*)(offset + ((size_t)(nb * 4096 + hw)) * 18 + 2 * tap);
                const float py = (float)(h + (tap / 3) - 1) + dydx.x;
                const float px = (float)(w + (tap % 3) - 1) + dydx.y;
                const float fy = floorf(py), fx = floorf(px);
                const float wy = py - fy, wx = px - fx;
                const int iy0 = (int)fy, ix0 = (int)fx;
                const float cw[4] = {(1.f - wy) * (1.f - wx), (1.f - wy) * wx, wy * (1.f - wx), wy * wx};
#pragma unroll
                for (int q = 0; q < 4; q++) {
                    const int iy = iy0 + (q >> 1);
                    const int ix = ix0 + (q & 1);
                    const bool valid = (iy >= 0) && (iy < HH) && (ix >= 0) && (ix < WW);
                    const int iyc = min(max(iy, 0), HH - 1);
                    const int ixc = min(max(ix, 0), WW - 1);
                    s_addr[q * 128 + p] = ((nb * HH + iyc) * WW + ixc) * C_IN;
                    s_wgt[q * 128 + p]  = valid ? cw[q] : 0.f;
                }
            }
            __syncthreads();
        }

        // ---- A-gen: this thread = (pos, 16 channels), bf16 hi/lo ----
        {
            const int c0 = cb * 64 + q4 * 16;
            const int a0 = s_addr[pos]        + c0;
            const int a1 = s_addr[128 + pos]  + c0;
            const int a2 = s_addr[256 + pos]  + c0;
            const int a3 = s_addr[384 + pos]  + c0;
            const float q0 = s_wgt[pos],       q1 = s_wgt[128 + pos];
            const float q2 = s_wgt[256 + pos], q3 = s_wgt[384 + pos];
#pragma unroll
            for (int half = 0; half < 2; half++) {
                const int c = half * 8;
                const float4 pa0 = *(const float4*)(g_xT + a0 + c);
                const float4 pa1 = *(const float4*)(g_xT + a0 + c + 4);
                const float4 pb0 = *(const float4*)(g_xT + a1 + c);
                const float4 pb1 = *(const float4*)(g_xT + a1 + c + 4);
                const float4 pc0 = *(const float4*)(g_xT + a2 + c);
                const float4 pc1 = *(const float4*)(g_xT + a2 + c + 4);
                const float4 pd0 = *(const float4*)(g_xT + a3 + c);
                const float4 pd1 = *(const float4*)(g_xT + a3 + c + 4);
                float v[8];
                v[0] = q0 * pa0.x + q1 * pb0.x + q2 * pc0.x + q3 * pd0.x;
                v[1] = q0 * pa0.y + q1 * pb0.y + q2 * pc0.y + q3 * pd0.y;
                v[2] = q0 * pa0.z + q1 * pb0.z + q2 * pc0.z + q3 * pd0.z;
                v[3] = q0 * pa0.w + q1 * pb0.w + q2 * pc0.w + q3 * pd0.w;
                v[4] = q0 * pa1.x + q1 * pb1.x + q2 * pc1.x + q3 * pd1.x;
                v[5] = q0 * pa1.y + q1 * pb1.y + q2 * pc1.y + q3 * pd1.y;
                v[6] = q0 * pa1.z + q1 * pb1.z + q2 * pc1.z + q3 * pd1.z;
                v[7] = q0 * pa1.w + q1 * pb1.w + q2 * pc1.w + q3 * pd1.w;
                uint32_t h[4], l[4];
#pragma unroll
                for (int j = 0; j < 4; j++) {
                    h[j] = packbf(v[2 * j], v[2 * j + 1]);
                    const float e0 = v[2 * j]     - __uint_as_float(h[j] << 16);
                    const float e1 = v[2 * j + 1] - __uint_as_float(h[j] & 0xFFFF0000u);
                    l[j] = packbf(e0, e1);
                }
                sts128(aGen + half * 16,         h[0], h[1], h[2], h[3]);
                sts128(aGen + ATILE + half * 16, l[0], l[1], l[2], l[3]);
            }
        }

        // wait for this chunk's B (leave next chunk's group pending)
        if (chunk + 1 < NCHUNK) asm volatile("cp.async.wait_group 1;" ::: "memory");
        else                    asm volatile("cp.async.wait_group 0;" ::: "memory");
        __syncthreads();

        // ---- MMA: 4 k16 steps, 3 hi/lo products ----
        const uint32_t bHi = sb + SM_B + (uint32_t)s * BCHUNK + bRowO;
        const uint32_t bLo = bHi + BTILE;
#pragma unroll
        for (int ks = 0; ks < 4; ks++) {
            const uint32_t kb = (uint32_t)ks << 5;
            uint32_t ah[8], bh[16], al[8];
            ldsm4(ah,     aBase + kb);
            ldsm4(ah + 4, aBase + 16 * BROW + kb);
#pragma unroll
            for (int j = 0; j < 4; j++) ldsm4(bh + j * 4, bHi + (uint32_t)j * 16 * BROW + kb);
            mma_all(acc, ah, bh);                       // Ah*Bh
            ldsm4(al,     aBase + ATILE + kb);
            ldsm4(al + 4, aBase + ATILE + 16 * BROW + kb);
            mma_all(acc, al, bh);                       // Al*Bh
#pragma unroll
            for (int j = 0; j < 4; j++) ldsm4(bh + j * 4, bLo + (uint32_t)j * 16 * BROW + kb);
            mma_all(acc, ah, bh);                       // Ah*Bl
        }
    }

    // ---- Epilogue: direct stores (sector-dense: 8 consecutive m per o) ----
    const int g  = lane >> 2;
    const int tt = lane & 3;
#pragma unroll
    for (int mt = 0; mt < 2; mt++) {
        const int m = wm * 32 + mt * 16 + g;
        float* pm = out + hwb + m;
#pragma unroll
        for (int nn = 0; nn < 8; nn++) {
            const int o = wn * 64 + nn * 8 + tt * 2;
            float* p = pm + ((size_t)(nb * O_OUT + o) << 12);
            p[0]        = acc[mt][nn][0];
            p[4096]     = acc[mt][nn][1];
            p[8]        = acc[mt][nn][2];
            p[4096 + 8] = acc[mt][nn][3];
        }
    }
}

// ---------------------------------------------------------------------------
extern "C" void kernel_launch(void* const* d_in, const int* in_sizes, int n_in,
                              void* d_out, int out_size) {
    (void)out_size;
    const float* x = nullptr;
    const float* offset = nullptr;
    const float* weight = nullptr;
    for (int i = 0; i < n_in; i++) {
        const int sz = in_sizes[i];
        if (sz == NB * C_IN * HH * WW)    x = (const float*)d_in[i];
        else if (sz == NB * HH * WW * 18) offset = (const float*)d_in[i];
        else if (sz == O_OUT * C_IN * 9)  weight = (const float*)d_in[i];
    }
    float* out = (float*)d_out;

    cudaFuncSetAttribute(deform_mma_kernel, cudaFuncAttributeMaxDynamicSharedMemorySize, SMEM_BYTES);

    transpose_x_kernel<<<dim3(16, NB * HH), 256>>>(x);
    prep_w_kernel<<<(NCHUNK * 8192 + 255) / 256, 256>>>(weight);
    deform_mma_kernel<<<128, 512, SMEM_BYTES>>>(offset, out);
}

// round 8
// speedup vs baseline: 2.4402x; 1.2777x over previous
#include <cuda_runtime.h>
#include <cuda_fp16.h>
#include <math.h>
#include <stdint.h>

// Problem constants
#define NB    4
#define HH    64
#define WW    64
#define C_IN  256
#define O_OUT 256
#define NCHUNK 36            // 9 taps * 4 channel-blocks of 64
// GEMM: M=16384 (positions), N=256 (outputs), K=2304 (tap-major)

// Tiles: rows padded to 144B (9 x 16B) for conflict-free ldmatrix/STS
#define BROW    144
#define BTILE   36864        // 256 o x 144 B   (fp16 hi)  ; lo at +BTILE
#define BCHUNK  73728        // hi + lo
#define ATILE   18432        // 128 m x 144 B   (single fp16)

// Scratch (__device__ globals per allocation-free rule)
__device__ float g_xT[(size_t)NB * HH * WW * C_IN];                 // [n][h][w][c]
__device__ __align__(128) unsigned char g_wB[(size_t)NCHUNK * BCHUNK];

// ---------------- PTX helpers (non-'a' features only) ----------------
__device__ __forceinline__ uint32_t smem_u32(const void* p) {
    uint32_t a;
    asm("{ .reg .u64 t; cvta.to.shared.u64 t, %1; cvt.u32.u64 %0, t; }" : "=r"(a) : "l"(p));
    return a;
}
__device__ __forceinline__ void ldsm4(uint32_t* r, uint32_t addr) {
    asm volatile("ldmatrix.sync.aligned.m8n8.x4.shared.b16 {%0,%1,%2,%3}, [%4];"
        : "=r"(r[0]), "=r"(r[1]), "=r"(r[2]), "=r"(r[3]) : "r"(addr));
}
__device__ __forceinline__ void cpasync16(uint32_t dst, const void* src) {
    asm volatile("cp.async.cg.shared.global [%0], [%1], 16;" :: "r"(dst), "l"(src) : "memory");
}
__device__ __forceinline__ void sts128(uint32_t addr, uint32_t a, uint32_t b, uint32_t c, uint32_t d) {
    asm volatile("st.shared.v4.b32 [%0], {%1, %2, %3, %4};" :: "r"(addr), "r"(a), "r"(b), "r"(c), "r"(d) : "memory");
}
__device__ __forceinline__ uint32_t packh(float lo, float hi) {
    uint32_t r; asm("cvt.rn.f16x2.f32 %0, %1, %2;" : "=r"(r) : "f"(hi), "f"(lo)); return r;  // low16 = lo
}
// 16 warp-MMAs: full 32(M) x 64(N) warp tile, one k16 step (fp16 in, fp32 acc)
__device__ __forceinline__ void mma_all(float (&acc)[2][8][4], const uint32_t* a, const uint32_t* b) {
#pragma unroll
    for (int mt = 0; mt < 2; mt++)
#pragma unroll
        for (int nn = 0; nn < 8; nn++) {
            const uint32_t* bb = b + (nn >> 1) * 4 + (nn & 1) * 2;
            asm volatile("mma.sync.aligned.m16n8k16.row.col.f32.f16.f16.f32 "
                "{%0,%1,%2,%3}, {%4,%5,%6,%7}, {%8,%9}, {%0,%1,%2,%3};"
                : "+f"(acc[mt][nn][0]), "+f"(acc[mt][nn][1]), "+f"(acc[mt][nn][2]), "+f"(acc[mt][nn][3])
                : "r"(a[mt * 4]), "r"(a[mt * 4 + 1]), "r"(a[mt * 4 + 2]), "r"(a[mt * 4 + 3]),
                  "r"(bb[0]), "r"(bb[1]));
        }
}

// -------- smem layout (dynamic) --------
#define SM_ADDR   64        // int   [2 dstage][4 corner][128]  = 4096 B
#define SM_WGT    4160      // float [2 dstage][4 corner][128]  = 4096 B
#define SM_A      8320      // 2 stages x 18432
#define SM_B      45184     // 2 stages x 73728
#define SMEM_BYTES 192640

// ---------------------------------------------------------------------------
// x: [N,C,H,W] -> [N,H,W,C]
// ---------------------------------------------------------------------------
__global__ void transpose_x_kernel(const float* __restrict__ x) {
    __shared__ float tile[32][33];
    const int nh = blockIdx.y;
    const int c0 = (blockIdx.x >> 1) << 5;
    const int w0 = (blockIdx.x & 1) << 5;
    const int tx = threadIdx.x & 31;
    const int ty = threadIdx.x >> 5;
    const int n  = nh >> 6;
    const int h  = nh & 63;

    const float* xp = x + ((size_t)n * C_IN + c0) * (HH * WW) + h * WW + w0;
#pragma unroll
    for (int i = 0; i < 32; i += 8)
        tile[ty + i][tx] = xp[(size_t)(ty + i) * (HH * WW) + tx];
    __syncthreads();
    float* op = g_xT + ((size_t)nh * WW + w0) * C_IN + c0;
#pragma unroll
    for (int i = 0; i < 32; i += 8)
        op[(size_t)(ty + i) * C_IN + tx] = tile[tx][ty + i];
}

// ---------------------------------------------------------------------------
// weight [O,C,3,3] fp32 -> fp16 hi/lo padded-row B tiles per chunk
// ---------------------------------------------------------------------------
__global__ void prep_w_kernel(const float* __restrict__ w) {
    int idx = blockIdx.x * 256 + threadIdx.x;          // 0 .. 36*8192-1
    if (idx >= NCHUNK * 8192) return;
    const int chunk = idx >> 13;
    const int r  = idx & 8191;
    const int o  = r >> 5;          // 0..255
    const int j2 = r & 31;          // fp16-pair index within 64-ch row
    const int tap = chunk >> 2, cb = chunk & 3;
    const int c = cb * 64 + 2 * j2;
    const float v0 = w[(o * C_IN + c) * 9 + tap];
    const float v1 = w[(o * C_IN + c + 1) * 9 + tap];
    __half2 h = __floats2half2_rn(v0, v1);
    __half2 l = __floats2half2_rn(v0 - __low2float(h), v1 - __high2float(h));
    unsigned char* base = g_wB + (size_t)chunk * BCHUNK + (size_t)o * BROW + j2 * 4;
    *(uint32_t*)(base)         = *(uint32_t*)&h;
    *(uint32_t*)(base + BTILE) = *(uint32_t*)&l;
}

// ---------------------------------------------------------------------------
// Fused bilinear-im2col + fp16 (A single, B split) mma.sync GEMM.
// grid = 128 CTAs (4 n x 32 tiles of 128 positions), 512 threads, 1 CTA/SM.
// Warp layout: 16 warps = 4(M blocks of 32) x 4(N blocks of 64).
// Pipelined: MMA(k) overlaps A-gen(k+1) and B prefetch(k+1).
// ---------------------------------------------------------------------------
__global__ __launch_bounds__(512, 1)
void deform_mma_kernel(const float* __restrict__ offset, float* __restrict__ out) {
    extern __shared__ char smem[];
    const uint32_t sb = smem_u32(smem);
    const int t    = threadIdx.x;
    const int blk  = blockIdx.x;           // 0..127
    const int nb   = blk >> 5;
    const int hwb  = (blk & 31) * 128;
    const int warp = t >> 5, lane = t & 31;
    const int wm = warp & 3, wn = warp >> 2;

    int*   s_addr = (int*)(smem + SM_ADDR);    // [dstage][corner][128]
    float* s_wgt  = (float*)(smem + SM_WGT);

    float acc[2][8][4];
#pragma unroll
    for (int mt = 0; mt < 2; mt++)
#pragma unroll
        for (int nn = 0; nn < 8; nn++)
#pragma unroll
            for (int q = 0; q < 4; q++) acc[mt][nn][q] = 0.f;

    // per-thread constant addressing
    const int pos = t & 127;        // A-gen: position
    const int q4  = t >> 7;         // A-gen: 16-channel group (0..3)
    const uint32_t aGenB = sb + SM_A + pos * BROW + q4 * 32;
    const uint32_t aBase = sb + SM_A + (wm * 32 + (lane & 15)) * BROW + ((lane >> 4) << 4);
    const uint32_t bRowO = (uint32_t)(wn * 64 + (lane & 7) + ((lane >> 4) << 3)) * BROW
                         + (((lane >> 3) & 1) << 4);

    // ---- descriptor generator (bilinear corners for one tap) ----
    auto desc_gen = [&](int tap, int ds) {
        if (t < 128) {
            const int p  = t;
            const int hw = hwb + p;
            const int h  = hw >> 6, w = hw & 63;
            const float2 dydx = *(const float2*)(offset + ((size_t)(nb * 4096 + hw)) * 18 + 2 * tap);
            const float py = (float)(h + (tap / 3) - 1) + dydx.x;
            const float px = (float)(w + (tap % 3) - 1) + dydx.y;
            const float fy = floorf(py), fx = floorf(px);
            const float wy = py - fy, wx = px - fx;
            const int iy0 = (int)fy, ix0 = (int)fx;
            const float cw[4] = {(1.f - wy) * (1.f - wx), (1.f - wy) * wx, wy * (1.f - wx), wy * wx};
#pragma unroll
            for (int q = 0; q < 4; q++) {
                const int iy = iy0 + (q >> 1);
                const int ix = ix0 + (q & 1);
                const bool valid = (iy >= 0) && (iy < HH) && (ix >= 0) && (ix < WW);
                const int iyc = min(max(iy, 0), HH - 1);
                const int ixc = min(max(ix, 0), WW - 1);
                s_addr[(ds * 4 + q) * 128 + p] = ((nb * HH + iyc) * WW + ixc) * C_IN;
                s_wgt[(ds * 4 + q) * 128 + p]  = valid ? cw[q] : 0.f;
            }
        }
    };

    // ---- A-tile generator: this thread = (pos, 16 channels), single fp16 ----
    auto a_gen = [&](int chunk, int as, int ds) {
        const int cb = chunk & 3;
        const int c0 = cb * 64 + q4 * 16;
        const int base = ds * 4 * 128 + pos;
        const int a0 = s_addr[base]       + c0;
        const int a1 = s_addr[base + 128] + c0;
        const int a2 = s_addr[base + 256] + c0;
        const int a3 = s_addr[base + 384] + c0;
        const float q0 = s_wgt[base],       q1 = s_wgt[base + 128];
        const float q2 = s_wgt[base + 256], q3 = s_wgt[base + 384];
        const uint32_t dst = aGenB + (uint32_t)as * ATILE;
#pragma unroll
        for (int half = 0; half < 2; half++) {
            const int c = half * 8;
            const float4 pa0 = *(const float4*)(g_xT + a0 + c);
            const float4 pa1 = *(const float4*)(g_xT + a0 + c + 4);
            const float4 pb0 = *(const float4*)(g_xT + a1 + c);
            const float4 pb1 = *(const float4*)(g_xT + a1 + c + 4);
            const float4 pc0 = *(const float4*)(g_xT + a2 + c);
            const float4 pc1 = *(const float4*)(g_xT + a2 + c + 4);
            const float4 pd0 = *(const float4*)(g_xT + a3 + c);
            const float4 pd1 = *(const float4*)(g_xT + a3 + c + 4);
            float v[8];
            v[0] = q0 * pa0.x + q1 * pb0.x + q2 * pc0.x + q3 * pd0.x;
            v[1] = q0 * pa0.y + q1 * pb0.y + q2 * pc0.y + q3 * pd0.y;
            v[2] = q0 * pa0.z + q1 * pb0.z + q2 * pc0.z + q3 * pd0.z;
            v[3] = q0 * pa0.w + q1 * pb0.w + q2 * pc0.w + q3 * pd0.w;
            v[4] = q0 * pa1.x + q1 * pb1.x + q2 * pc1.x + q3 * pd1.x;
            v[5] = q0 * pa1.y + q1 * pb1.y + q2 * pc1.y + q3 * pd1.y;
            v[6] = q0 * pa1.z + q1 * pb1.z + q2 * pc1.z + q3 * pd1.z;
            v[7] = q0 * pa1.w + q1 * pb1.w + q2 * pc1.w + q3 * pd1.w;
            sts128(dst + half * 16,
                   packh(v[0], v[1]), packh(v[2], v[3]),
                   packh(v[4], v[5]), packh(v[6], v[7]));
        }
    };

    // ---- B prefetch ----
    auto b_fetch = [&](int chunk) {
        const uint32_t dst = sb + SM_B + (uint32_t)(chunk & 1) * BCHUNK;
        const unsigned char* src = g_wB + (size_t)chunk * BCHUNK;
#pragma unroll
        for (int i = 0; i < 9; i++) {
            const int off = (t + i * 512) * 16;
            cpasync16(dst + off, src + off);
        }
        asm volatile("cp.async.commit_group;" ::: "memory");
    };

    // ================= prologue =================
    desc_gen(0, 0);
    b_fetch(0);
    __syncthreads();                 // desc(0) visible
    a_gen(0, 0, 0);
    asm volatile("cp.async.wait_group 0;" ::: "memory");
    __syncthreads();                 // A(0), B(0) ready

    // ================= main loop =================
    for (int k = 0; k < NCHUNK; k++) {
        const int s = k & 1;
        if (k + 1 < NCHUNK) b_fetch(k + 1);

        // ---- MMA(k): 4 k16 steps, 2 products (A*Bh + A*Bl) ----
        const uint32_t bHi = sb + SM_B + (uint32_t)s * BCHUNK + bRowO;
        const uint32_t bLo = bHi + BTILE;
        const uint32_t aB  = aBase + (uint32_t)s * ATILE;
#pragma unroll
        for (int ks = 0; ks < 4; ks++) {
            const uint32_t kb = (uint32_t)ks << 5;
            uint32_t ah[8], bh[16];
            ldsm4(ah,     aB + kb);
            ldsm4(ah + 4, aB + 16 * BROW + kb);
#pragma unroll
            for (int j = 0; j < 4; j++) ldsm4(bh + j * 4, bHi + (uint32_t)j * 16 * BROW + kb);
            mma_all(acc, ah, bh);                       // A*Bh
#pragma unroll
            for (int j = 0; j < 4; j++) ldsm4(bh + j * 4, bLo + (uint32_t)j * 16 * BROW + kb);
            mma_all(acc, ah, bh);                       // A*Bl
        }

        // ---- descriptors for the tap after next (double-buffered) ----
        if ((k + 2) < NCHUNK && (((k + 2) & 3) == 0))
            desc_gen((k + 2) >> 2, ((k + 2) >> 2) & 1);

        // ---- A-gen(k+1) overlapped with MMA pipe drain ----
        if (k + 1 < NCHUNK) {
            a_gen(k + 1, (k + 1) & 1, ((k + 1) >> 2) & 1);
            asm volatile("cp.async.wait_group 0;" ::: "memory");
        }
        __syncthreads();
    }

    // ---- Epilogue: direct stores (sector-dense: 8 consecutive m per o) ----
    const int g  = lane >> 2;
    const int tt = lane & 3;
#pragma unroll
    for (int mt = 0; mt < 2; mt++) {
        const int m = wm * 32 + mt * 16 + g;
        float* pm = out + hwb + m;
#pragma unroll
        for (int nn = 0; nn < 8; nn++) {
            const int o = wn * 64 + nn * 8 + tt * 2;
            float* p = pm + ((size_t)(nb * O_OUT + o) << 12);
            p[0]        = acc[mt][nn][0];
            p[4096]     = acc[mt][nn][1];
            p[8]        = acc[mt][nn][2];
            p[4096 + 8] = acc[mt][nn][3];
        }
    }
}

// ---------------------------------------------------------------------------
extern "C" void kernel_launch(void* const* d_in, const int* in_sizes, int n_in,
                              void* d_out, int out_size) {
    (void)out_size;
    const float* x = nullptr;
    const float* offset = nullptr;
    const float* weight = nullptr;
    for (int i = 0; i < n_in; i++) {
        const int sz = in_sizes[i];
        if (sz == NB * C_IN * HH * WW)    x = (const float*)d_in[i];
        else if (sz == NB * HH * WW * 18) offset = (const float*)d_in[i];
        else if (sz == O_OUT * C_IN * 9)  weight = (const float*)d_in[i];
    }
    float* out = (float*)d_out;

    cudaFuncSetAttribute(deform_mma_kernel, cudaFuncAttributeMaxDynamicSharedMemorySize, SMEM_BYTES);

    transpose_x_kernel<<<dim3(16, NB * HH), 256>>>(x);
    prep_w_kernel<<<(NCHUNK * 8192 + 255) / 256, 256>>>(weight);
    deform_mma_kernel<<<128, 512, SMEM_BYTES>>>(offset, out);
}

// round 10
// speedup vs baseline: 4.2815x; 1.7546x over previous
#include <cuda_runtime.h>
#include <cuda_fp16.h>
#include <math.h>
#include <stdint.h>

// Problem constants
#define NB    4
#define HH    64
#define WW    64
#define C_IN  256
#define O_OUT 256
#define NCHUNK 36            // 9 taps * 4 channel-blocks of 64
// GEMM: M=16384 (positions), N=256 (outputs), K=2304 (tap-major)

// Tiles: rows padded to 144B (9 x 16B) for conflict-free ldmatrix/STS
#define BROW    144
#define BTILE   36864        // 256 o x 144 B (single fp16 B tile per chunk)
#define ATILE   18432        // 128 m x 144 B (single fp16 A tile)

// Scratch (__device__ globals per allocation-free rule)
__device__ __half g_xTh[(size_t)NB * HH * WW * C_IN];               // [n][h][w][c] fp16
__device__ __align__(128) unsigned char g_wB[(size_t)NCHUNK * BTILE];

// ---------------- PTX helpers (non-'a' features only) ----------------
__device__ __forceinline__ uint32_t smem_u32(const void* p) {
    uint32_t a;
    asm("{ .reg .u64 t; cvta.to.shared.u64 t, %1; cvt.u32.u64 %0, t; }" : "=r"(a) : "l"(p));
    return a;
}
__device__ __forceinline__ void ldsm4(uint32_t* r, uint32_t addr) {
    asm volatile("ldmatrix.sync.aligned.m8n8.x4.shared.b16 {%0,%1,%2,%3}, [%4];"
        : "=r"(r[0]), "=r"(r[1]), "=r"(r[2]), "=r"(r[3]) : "r"(addr));
}
__device__ __forceinline__ void cpasync16(uint32_t dst, const void* src) {
    asm volatile("cp.async.cg.shared.global [%0], [%1], 16;" :: "r"(dst), "l"(src) : "memory");
}
__device__ __forceinline__ void sts128(uint32_t addr, uint32_t a, uint32_t b, uint32_t c, uint32_t d) {
    asm volatile("st.shared.v4.b32 [%0], {%1, %2, %3, %4};" :: "r"(addr), "r"(a), "r"(b), "r"(c), "r"(d) : "memory");
}
__device__ __forceinline__ uint32_t packh(float lo, float hi) {
    uint32_t r; asm("cvt.rn.f16x2.f32 %0, %1, %2;" : "=r"(r) : "f"(hi), "f"(lo)); return r;  // low16 = lo
}
// 16 warp-MMAs: full 32(M) x 64(N) warp tile, one k16 step (fp16 in, fp32 acc)
__device__ __forceinline__ void mma_all(float (&acc)[2][8][4], const uint32_t* a, const uint32_t* b) {
#pragma unroll
    for (int mt = 0; mt < 2; mt++)
#pragma unroll
        for (int nn = 0; nn < 8; nn++) {
            const uint32_t* bb = b + (nn >> 1) * 4 + (nn & 1) * 2;
            asm volatile("mma.sync.aligned.m16n8k16.row.col.f32.f16.f16.f32 "
                "{%0,%1,%2,%3}, {%4,%5,%6,%7}, {%8,%9}, {%0,%1,%2,%3};"
                : "+f"(acc[mt][nn][0]), "+f"(acc[mt][nn][1]), "+f"(acc[mt][nn][2]), "+f"(acc[mt][nn][3])
                : "r"(a[mt * 4]), "r"(a[mt * 4 + 1]), "r"(a[mt * 4 + 2]), "r"(a[mt * 4 + 3]),
                  "r"(bb[0]), "r"(bb[1]));
        }
}

// -------- smem layout (dynamic) --------
#define SM_ADDR   64        // int   [2 dstage][4 corner][128]  = 4096 B
#define SM_WGT    4160      // float [2 dstage][4 corner][128]  = 4096 B
#define SM_A      8320      // 2 stages x 18432
#define SM_B      45184     // 2 stages x 36864
#define SMEM_BYTES 118912

// ---------------------------------------------------------------------------
// x: [N,C,H,W] fp32 -> [N,H,W,C] fp16
// ---------------------------------------------------------------------------
__global__ void transpose_x_kernel(const float* __restrict__ x) {
    __shared__ float tile[32][33];
    const int nh = blockIdx.y;
    const int c0 = (blockIdx.x >> 1) << 5;
    const int w0 = (blockIdx.x & 1) << 5;
    const int tx = threadIdx.x & 31;
    const int ty = threadIdx.x >> 5;
    const int n  = nh >> 6;
    const int h  = nh & 63;

    const float* xp = x + ((size_t)n * C_IN + c0) * (HH * WW) + h * WW + w0;
#pragma unroll
    for (int i = 0; i < 32; i += 8)
        tile[ty + i][tx] = xp[(size_t)(ty + i) * (HH * WW) + tx];
    __syncthreads();
    __half* op = g_xTh + ((size_t)nh * WW + w0) * C_IN + c0;
#pragma unroll
    for (int i = 0; i < 32; i += 8)
        op[(size_t)(ty + i) * C_IN + tx] = __float2half(tile[tx][ty + i]);
}

// ---------------------------------------------------------------------------
// weight [O,C,3,3] fp32 -> fp16 padded-row B tiles per chunk
// ---------------------------------------------------------------------------
__global__ void prep_w_kernel(const float* __restrict__ w) {
    int idx = blockIdx.x * 256 + threadIdx.x;          // 0 .. 36*8192-1
    if (idx >= NCHUNK * 8192) return;
    const int chunk = idx >> 13;
    const int r  = idx & 8191;
    const int o  = r >> 5;          // 0..255
    const int j2 = r & 31;          // fp16-pair index within 64-ch row
    const int tap = chunk >> 2, cb = chunk & 3;
    const int c = cb * 64 + 2 * j2;
    const float v0 = w[(o * C_IN + c) * 9 + tap];
    const float v1 = w[(o * C_IN + c + 1) * 9 + tap];
    __half2 h = __floats2half2_rn(v0, v1);
    *(uint32_t*)(g_wB + (size_t)chunk * BTILE + (size_t)o * BROW + j2 * 4) = *(uint32_t*)&h;
}

// ---------------------------------------------------------------------------
// Fused bilinear-im2col + fp16 mma.sync GEMM (single product).
// grid = 128 CTAs (4 n x 32 tiles of 128 positions), 512 threads, 1 CTA/SM.
// Warp layout: 16 warps = 4(M blocks of 32) x 4(N blocks of 64).
// Pipelined: MMA(k) overlaps A-gen(k+1) and B prefetch(k+1).
// ---------------------------------------------------------------------------
__global__ __launch_bounds__(512, 1)
void deform_mma_kernel(const float* __restrict__ offset, float* __restrict__ out) {
    extern __shared__ char smem[];
    const uint32_t sb = smem_u32(smem);
    const int t    = threadIdx.x;
    const int blk  = blockIdx.x;           // 0..127
    const int nb   = blk >> 5;
    const int hwb  = (blk & 31) * 128;
    const int warp = t >> 5, lane = t & 31;
    const int wm = warp & 3, wn = warp >> 2;

    int*   s_addr = (int*)(smem + SM_ADDR);    // [dstage][corner][128]
    float* s_wgt  = (float*)(smem + SM_WGT);

    float acc[2][8][4];
#pragma unroll
    for (int mt = 0; mt < 2; mt++)
#pragma unroll
        for (int nn = 0; nn < 8; nn++)
#pragma unroll
            for (int q = 0; q < 4; q++) acc[mt][nn][q] = 0.f;

    // per-thread constant addressing
    const int pos = t & 127;        // A-gen: position
    const int q4  = t >> 7;         // A-gen: 16-channel group (0..3)
    const uint32_t aGenB = sb + SM_A + pos * BROW + q4 * 32;
    const uint32_t aBase = sb + SM_A + (wm * 32 + (lane & 15)) * BROW + ((lane >> 4) << 4);
    const uint32_t bRowO = (uint32_t)(wn * 64 + (lane & 7) + ((lane >> 4) << 3)) * BROW
                         + (((lane >> 3) & 1) << 4);

    // ---- descriptor generator (bilinear corners for one tap) ----
    auto desc_gen = [&](int tap, int ds) {
        if (t < 128) {
            const int p  = t;
            const int hw = hwb + p;
            const int h  = hw >> 6, w = hw & 63;
            const float2 dydx = *(const float2*)(offset + ((size_t)(nb * 4096 + hw)) * 18 + 2 * tap);
            const float py = (float)(h + (tap / 3) - 1) + dydx.x;
            const float px = (float)(w + (tap % 3) - 1) + dydx.y;
            const float fy = floorf(py), fx = floorf(px);
            const float wy = py - fy, wx = px - fx;
            const int iy0 = (int)fy, ix0 = (int)fx;
            const float cw[4] = {(1.f - wy) * (1.f - wx), (1.f - wy) * wx, wy * (1.f - wx), wy * wx};
#pragma unroll
            for (int q = 0; q < 4; q++) {
                const int iy = iy0 + (q >> 1);
                const int ix = ix0 + (q & 1);
                const bool valid = (iy >= 0) && (iy < HH) && (ix >= 0) && (ix < WW);
                const int iyc = min(max(iy, 0), HH - 1);
                const int ixc = min(max(ix, 0), WW - 1);
                s_addr[(ds * 4 + q) * 128 + p] = ((nb * HH + iyc) * WW + ixc) * C_IN;
                s_wgt[(ds * 4 + q) * 128 + p]  = valid ? cw[q] : 0.f;
            }
        }
    };

    // ---- A-tile generator: this thread = (pos, 16 channels), fp16 in/out ----
    auto a_gen = [&](int chunk, int as, int ds) {
        const int cb = chunk & 3;
        const int c0 = cb * 64 + q4 * 16;
        const int base = ds * 4 * 128 + pos;
        const int a0 = s_addr[base]       + c0;
        const int a1 = s_addr[base + 128] + c0;
        const int a2 = s_addr[base + 256] + c0;
        const int a3 = s_addr[base + 384] + c0;
        const float q0 = s_wgt[base],       q1 = s_wgt[base + 128];
        const float q2 = s_wgt[base + 256], q3 = s_wgt[base + 384];
        // 16 channels = 2 x uint4 (8 half2) per corner
        uint4 u0a = *(const uint4*)(g_xTh + a0);
        uint4 u0b = *(const uint4*)(g_xTh + a0 + 8);
        uint4 u1a = *(const uint4*)(g_xTh + a1);
        uint4 u1b = *(const uint4*)(g_xTh + a1 + 8);
        uint4 u2a = *(const uint4*)(g_xTh + a2);
        uint4 u2b = *(const uint4*)(g_xTh + a2 + 8);
        uint4 u3a = *(const uint4*)(g_xTh + a3);
        uint4 u3b = *(const uint4*)(g_xTh + a3 + 8);
        const uint32_t* p0 = (const uint32_t*)&u0a;   // u0a..u0b contiguous on stack
        const uint32_t* p1 = (const uint32_t*)&u1a;
        const uint32_t* p2 = (const uint32_t*)&u2a;
        const uint32_t* p3 = (const uint32_t*)&u3a;
        uint32_t o[8];
#pragma unroll
        for (int j = 0; j < 8; j++) {
            const uint32_t w0 = (j < 4) ? p0[j] : ((const uint32_t*)&u0b)[j - 4];
            const uint32_t w1 = (j < 4) ? p1[j] : ((const uint32_t*)&u1b)[j - 4];
            const uint32_t w2 = (j < 4) ? p2[j] : ((const uint32_t*)&u2b)[j - 4];
            const uint32_t w3 = (j < 4) ? p3[j] : ((const uint32_t*)&u3b)[j - 4];
            const float2 f0 = __half22float2(*(const __half2*)&w0);
            const float2 f1 = __half22float2(*(const __half2*)&w1);
            const float2 f2 = __half22float2(*(const __half2*)&w2);
            const float2 f3 = __half22float2(*(const __half2*)&w3);
            const float vx = q0 * f0.x + q1 * f1.x + q2 * f2.x + q3 * f3.x;
            const float vy = q0 * f0.y + q1 * f1.y + q2 * f2.y + q3 * f3.y;
            o[j] = packh(vx, vy);
        }
        const uint32_t dst = aGenB + (uint32_t)as * ATILE;
        sts128(dst,      o[0], o[1], o[2], o[3]);
        sts128(dst + 16, o[4], o[5], o[6], o[7]);
    };

    // ---- B prefetch: 36864 B per chunk ----
    auto b_fetch = [&](int chunk) {
        const uint32_t dst = sb + SM_B + (uint32_t)(chunk & 1) * BTILE;
        const unsigned char* src = g_wB + (size_t)chunk * BTILE;
#pragma unroll
        for (int i = 0; i < 4; i++) {
            const int off = (t + i * 512) * 16;
            cpasync16(dst + off, src + off);
        }
        if (t < 256) {
            const int off = (t + 2048) * 16;
            cpasync16(dst + off, src + off);
        }
        asm volatile("cp.async.commit_group;" ::: "memory");
    };

    // ================= prologue =================
    desc_gen(0, 0);
    b_fetch(0);
    __syncthreads();                 // desc(0) visible
    a_gen(0, 0, 0);
    asm volatile("cp.async.wait_group 0;" ::: "memory");
    __syncthreads();                 // A(0), B(0) ready

    // ================= main loop =================
    for (int k = 0; k < NCHUNK; k++) {
        const int s = k & 1;
        if (k + 1 < NCHUNK) b_fetch(k + 1);

        // ---- MMA(k): 4 k16 steps, single fp16 product ----
        const uint32_t bHi = sb + SM_B + (uint32_t)s * BTILE + bRowO;
        const uint32_t aB  = aBase + (uint32_t)s * ATILE;
#pragma unroll
        for (int ks = 0; ks < 4; ks++) {
            const uint32_t kb = (uint32_t)ks << 5;
            uint32_t ah[8], bh[16];
            ldsm4(ah,     aB + kb);
            ldsm4(ah + 4, aB + 16 * BROW + kb);
#pragma unroll
            for (int j = 0; j < 4; j++) ldsm4(bh + j * 4, bHi + (uint32_t)j * 16 * BROW + kb);
            mma_all(acc, ah, bh);
        }

        // ---- descriptors for the tap after next (double-buffered) ----
        if ((k + 2) < NCHUNK && (((k + 2) & 3) == 0))
            desc_gen((k + 2) >> 2, ((k + 2) >> 2) & 1);

        // ---- A-gen(k+1) overlapped with MMA pipe drain ----
        if (k + 1 < NCHUNK) {
            a_gen(k + 1, (k + 1) & 1, ((k + 1) >> 2) & 1);
            asm volatile("cp.async.wait_group 0;" ::: "memory");
        }
        __syncthreads();
    }

    // ---- Epilogue: direct stores (sector-dense: 8 consecutive m per o) ----
    const int g  = lane >> 2;
    const int tt = lane & 3;
#pragma unroll
    for (int mt = 0; mt < 2; mt++) {
        const int m = wm * 32 + mt * 16 + g;
        float* pm = out + hwb + m;
#pragma unroll
        for (int nn = 0; nn < 8; nn++) {
            const int o = wn * 64 + nn * 8 + tt * 2;
            float* p = pm + ((size_t)(nb * O_OUT + o) << 12);
            p[0]        = acc[mt][nn][0];
            p[4096]     = acc[mt][nn][1];
            p[8]        = acc[mt][nn][2];
            p[4096 + 8] = acc[mt][nn][3];
        }
    }
}

// ---------------------------------------------------------------------------
extern "C" void kernel_launch(void* const* d_in, const int* in_sizes, int n_in,
                              void* d_out, int out_size) {
    (void)out_size;
    const float* x = nullptr;
    const float* offset = nullptr;
    const float* weight = nullptr;
    for (int i = 0; i < n_in; i++) {
        const int sz = in_sizes[i];
        if (sz == NB * C_IN * HH * WW)    x = (const float*)d_in[i];
        else if (sz == NB * HH * WW * 18) offset = (const float*)d_in[i];
        else if (sz == O_OUT * C_IN * 9)  weight = (const float*)d_in[i];
    }
    float* out = (float*)d_out;

    cudaFuncSetAttribute(deform_mma_kernel, cudaFuncAttributeMaxDynamicSharedMemorySize, SMEM_BYTES);

    transpose_x_kernel<<<dim3(16, NB * HH), 256>>>(x);
    prep_w_kernel<<<(NCHUNK * 8192 + 255) / 256, 256>>>(weight);
    deform_mma_kernel<<<128, 512, SMEM_BYTES>>>(offset, out);
}

// round 11
// speedup vs baseline: 6.5978x; 1.5410x over previous
#include <cuda_runtime.h>
#include <cuda_fp16.h>
#include <math.h>
#include <stdint.h>

// Problem constants
#define NB    4
#define HH    64
#define WW    64
#define C_IN  256
#define O_OUT 256
#define NCHUNK 36            // 9 taps * 4 channel-blocks of 64
// GEMM: M=16384 (positions), N=256 (outputs), K=2304 (tap-major)

// Tiles: rows padded to 144B (9 x 16B) for conflict-free ldmatrix/STS
#define BROW    144
#define BTILE   36864        // 256 o x 144 B (single fp16 B tile per chunk)
#define ATILE   18432        // 128 m x 144 B (single fp16 A tile)

// Scratch (__device__ globals per allocation-free rule)
__device__ __half g_xTh[(size_t)NB * HH * WW * C_IN];               // [n][h][w][c] fp16
__device__ __align__(128) unsigned char g_wB[(size_t)NCHUNK * BTILE];

// ---------------- PTX helpers (non-'a' features only) ----------------
__device__ __forceinline__ uint32_t smem_u32(const void* p) {
    uint32_t a;
    asm("{ .reg .u64 t; cvta.to.shared.u64 t, %1; cvt.u32.u64 %0, t; }" : "=r"(a) : "l"(p));
    return a;
}
__device__ __forceinline__ void ldsm4(uint32_t* r, uint32_t addr) {
    asm volatile("ldmatrix.sync.aligned.m8n8.x4.shared.b16 {%0,%1,%2,%3}, [%4];"
        : "=r"(r[0]), "=r"(r[1]), "=r"(r[2]), "=r"(r[3]) : "r"(addr));
}
__device__ __forceinline__ void cpasync16(uint32_t dst, const void* src) {
    asm volatile("cp.async.cg.shared.global [%0], [%1], 16;" :: "r"(dst), "l"(src) : "memory");
}
__device__ __forceinline__ void sts128(uint32_t addr, uint32_t a, uint32_t b, uint32_t c, uint32_t d) {
    asm volatile("st.shared.v4.b32 [%0], {%1, %2, %3, %4};" :: "r"(addr), "r"(a), "r"(b), "r"(c), "r"(d) : "memory");
}
__device__ __forceinline__ uint32_t packh(float lo, float hi) {
    uint32_t r; asm("cvt.rn.f16x2.f32 %0, %1, %2;" : "=r"(r) : "f"(hi), "f"(lo)); return r;  // low16 = lo
}
// 16 warp-MMAs: full 32(M) x 64(N) warp tile, one k16 step (fp16 in, fp32 acc)
__device__ __forceinline__ void mma_all(float (&acc)[2][8][4], const uint32_t* a, const uint32_t* b) {
#pragma unroll
    for (int mt = 0; mt < 2; mt++)
#pragma unroll
        for (int nn = 0; nn < 8; nn++) {
            const uint32_t* bb = b + (nn >> 1) * 4 + (nn & 1) * 2;
            asm volatile("mma.sync.aligned.m16n8k16.row.col.f32.f16.f16.f32 "
                "{%0,%1,%2,%3}, {%4,%5,%6,%7}, {%8,%9}, {%0,%1,%2,%3};"
                : "+f"(acc[mt][nn][0]), "+f"(acc[mt][nn][1]), "+f"(acc[mt][nn][2]), "+f"(acc[mt][nn][3])
                : "r"(a[mt * 4]), "r"(a[mt * 4 + 1]), "r"(a[mt * 4 + 2]), "r"(a[mt * 4 + 3]),
                  "r"(bb[0]), "r"(bb[1]));
        }
}

// -------- smem layout (dynamic) --------
#define SM_ADDR   64        // int   [2 dstage][4 corner][128]  = 4096 B
#define SM_WGT    4160      // float [2 dstage][4 corner][128]  = 4096 B
#define SM_A      8320      // 2 stages x 18432
#define SM_B      45184     // 2 stages x 36864
#define SMEM_BYTES 118912

// ---------------------------------------------------------------------------
// x: [N,C,H,W] fp32 -> [N,H,W,C] fp16
// ---------------------------------------------------------------------------
__global__ void transpose_x_kernel(const float* __restrict__ x) {
    __shared__ float tile[32][33];
    const int nh = blockIdx.y;
    const int c0 = (blockIdx.x >> 1) << 5;
    const int w0 = (blockIdx.x & 1) << 5;
    const int tx = threadIdx.x & 31;
    const int ty = threadIdx.x >> 5;
    const int n  = nh >> 6;
    const int h  = nh & 63;

    const float* xp = x + ((size_t)n * C_IN + c0) * (HH * WW) + h * WW + w0;
#pragma unroll
    for (int i = 0; i < 32; i += 8)
        tile[ty + i][tx] = xp[(size_t)(ty + i) * (HH * WW) + tx];
    __syncthreads();
    __half* op = g_xTh + ((size_t)nh * WW + w0) * C_IN + c0;
#pragma unroll
    for (int i = 0; i < 32; i += 8)
        op[(size_t)(ty + i) * C_IN + tx] = __float2half(tile[tx][ty + i]);
}

// ---------------------------------------------------------------------------
// weight [O,C,3,3] fp32 -> fp16 padded-row B tiles per chunk
// ---------------------------------------------------------------------------
__global__ void prep_w_kernel(const float* __restrict__ w) {
    int idx = blockIdx.x * 256 + threadIdx.x;          // 0 .. 36*8192-1
    if (idx >= NCHUNK * 8192) return;
    const int chunk = idx >> 13;
    const int r  = idx & 8191;
    const int o  = r >> 5;          // 0..255
    const int j2 = r & 31;          // fp16-pair index within 64-ch row
    const int tap = chunk >> 2, cb = chunk & 3;
    const int c = cb * 64 + 2 * j2;
    const float v0 = w[(o * C_IN + c) * 9 + tap];
    const float v1 = w[(o * C_IN + c + 1) * 9 + tap];
    __half2 h = __floats2half2_rn(v0, v1);
    *(uint32_t*)(g_wB + (size_t)chunk * BTILE + (size_t)o * BROW + j2 * 4) = *(uint32_t*)&h;
}

// ---------------------------------------------------------------------------
// Fused bilinear-im2col + fp16 mma.sync GEMM (single product).
// grid = 128 CTAs (4 n x 32 tiles of 128 positions), 512 threads, 1 CTA/SM.
// Warp layout: 16 warps = 4(M blocks of 32) x 4(N blocks of 64).
// A-gen lane map: (pos = t>>2, cg = t&3) so the 4 lanes of one position hit
// ONE 128B line per corner load (8 wavefronts/instr instead of 32).
// ---------------------------------------------------------------------------
__global__ __launch_bounds__(512, 1)
void deform_mma_kernel(const float* __restrict__ offset, float* __restrict__ out) {
    extern __shared__ char smem[];
    const uint32_t sb = smem_u32(smem);
    const int t    = threadIdx.x;
    const int blk  = blockIdx.x;           // 0..127
    const int nb   = blk >> 5;
    const int hwb  = (blk & 31) * 128;
    const int warp = t >> 5, lane = t & 31;
    const int wm = warp & 3, wn = warp >> 2;

    int*   s_addr = (int*)(smem + SM_ADDR);    // [dstage][corner][128]
    float* s_wgt  = (float*)(smem + SM_WGT);

    float acc[2][8][4];
#pragma unroll
    for (int mt = 0; mt < 2; mt++)
#pragma unroll
        for (int nn = 0; nn < 8; nn++)
#pragma unroll
            for (int q = 0; q < 4; q++) acc[mt][nn][q] = 0.f;

    // per-thread constant addressing
    const int pos = t >> 2;         // A-gen: position (0..127)
    const int cg  = t & 3;          // A-gen: 16-channel group (0..3)
    const uint32_t aGenB = sb + SM_A + pos * BROW + cg * 32;
    const uint32_t aBase = sb + SM_A + (wm * 32 + (lane & 15)) * BROW + ((lane >> 4) << 4);
    const uint32_t bRowO = (uint32_t)(wn * 64 + (lane & 7) + ((lane >> 4) << 3)) * BROW
                         + (((lane >> 3) & 1) << 4);

    // ---- descriptor generator (bilinear corners for one tap) ----
    auto desc_gen = [&](int tap, int ds) {
        if (t < 128) {
            const int p  = t;
            const int hw = hwb + p;
            const int h  = hw >> 6, w = hw & 63;
            const float2 dydx = *(const float2*)(offset + ((size_t)(nb * 4096 + hw)) * 18 + 2 * tap);
            const float py = (float)(h + (tap / 3) - 1) + dydx.x;
            const float px = (float)(w + (tap % 3) - 1) + dydx.y;
            const float fy = floorf(py), fx = floorf(px);
            const float wy = py - fy, wx = px - fx;
            const int iy0 = (int)fy, ix0 = (int)fx;
            const float cw[4] = {(1.f - wy) * (1.f - wx), (1.f - wy) * wx, wy * (1.f - wx), wy * wx};
#pragma unroll
            for (int q = 0; q < 4; q++) {
                const int iy = iy0 + (q >> 1);
                const int ix = ix0 + (q & 1);
                const bool valid = (iy >= 0) && (iy < HH) && (ix >= 0) && (ix < WW);
                const int iyc = min(max(iy, 0), HH - 1);
                const int ixc = min(max(ix, 0), WW - 1);
                s_addr[(ds * 4 + q) * 128 + p] = ((nb * HH + iyc) * WW + ixc) * C_IN;
                s_wgt[(ds * 4 + q) * 128 + p]  = valid ? cw[q] : 0.f;
            }
        }
    };

    // ---- A-tile generator: this thread = (pos, 16 channels), fp16 in/out ----
    auto a_gen = [&](int chunk, int as, int ds) {
        const int cb = chunk & 3;
        const int c0 = cb * 64 + cg * 16;
        const int base = ds * 4 * 128 + pos;
        const int a0 = s_addr[base]       + c0;
        const int a1 = s_addr[base + 128] + c0;
        const int a2 = s_addr[base + 256] + c0;
        const int a3 = s_addr[base + 384] + c0;
        const float q0 = s_wgt[base],       q1 = s_wgt[base + 128];
        const float q2 = s_wgt[base + 256], q3 = s_wgt[base + 384];
        // 16 channels = 2 x uint4 (8 half2) per corner; 4 lanes of one pos
        // cover one 128B line per instruction.
        uint4 u0a = *(const uint4*)(g_xTh + a0);
        uint4 u0b = *(const uint4*)(g_xTh + a0 + 8);
        uint4 u1a = *(const uint4*)(g_xTh + a1);
        uint4 u1b = *(const uint4*)(g_xTh + a1 + 8);
        uint4 u2a = *(const uint4*)(g_xTh + a2);
        uint4 u2b = *(const uint4*)(g_xTh + a2 + 8);
        uint4 u3a = *(const uint4*)(g_xTh + a3);
        uint4 u3b = *(const uint4*)(g_xTh + a3 + 8);
        const uint32_t* p0 = (const uint32_t*)&u0a;
        const uint32_t* p1 = (const uint32_t*)&u1a;
        const uint32_t* p2 = (const uint32_t*)&u2a;
        const uint32_t* p3 = (const uint32_t*)&u3a;
        uint32_t o[8];
#pragma unroll
        for (int j = 0; j < 8; j++) {
            const uint32_t w0 = (j < 4) ? p0[j] : ((const uint32_t*)&u0b)[j - 4];
            const uint32_t w1 = (j < 4) ? p1[j] : ((const uint32_t*)&u1b)[j - 4];
            const uint32_t w2 = (j < 4) ? p2[j] : ((const uint32_t*)&u2b)[j - 4];
            const uint32_t w3 = (j < 4) ? p3[j] : ((const uint32_t*)&u3b)[j - 4];
            const float2 f0 = __half22float2(*(const __half2*)&w0);
            const float2 f1 = __half22float2(*(const __half2*)&w1);
            const float2 f2 = __half22float2(*(const __half2*)&w2);
            const float2 f3 = __half22float2(*(const __half2*)&w3);
            const float vx = q0 * f0.x + q1 * f1.x + q2 * f2.x + q3 * f3.x;
            const float vy = q0 * f0.y + q1 * f1.y + q2 * f2.y + q3 * f3.y;
            o[j] = packh(vx, vy);
        }
        const uint32_t dst = aGenB + (uint32_t)as * ATILE;
        sts128(dst,      o[0], o[1], o[2], o[3]);
        sts128(dst + 16, o[4], o[5], o[6], o[7]);
    };

    // ---- B prefetch: 36864 B per chunk ----
    auto b_fetch = [&](int chunk) {
        const uint32_t dst = sb + SM_B + (uint32_t)(chunk & 1) * BTILE;
        const unsigned char* src = g_wB + (size_t)chunk * BTILE;
#pragma unroll
        for (int i = 0; i < 4; i++) {
            const int off = (t + i * 512) * 16;
            cpasync16(dst + off, src + off);
        }
        if (t < 256) {
            const int off = (t + 2048) * 16;
            cpasync16(dst + off, src + off);
        }
        asm volatile("cp.async.commit_group;" ::: "memory");
    };

    // ================= prologue =================
    desc_gen(0, 0);
    b_fetch(0);
    __syncthreads();                 // desc(0) visible
    a_gen(0, 0, 0);
    asm volatile("cp.async.wait_group 0;" ::: "memory");
    __syncthreads();                 // A(0), B(0) ready

    // ================= main loop =================
    for (int k = 0; k < NCHUNK; k++) {
        const int s = k & 1;
        if (k + 1 < NCHUNK) b_fetch(k + 1);

        // ---- MMA(k): 4 k16 steps, single fp16 product ----
        const uint32_t bHi = sb + SM_B + (uint32_t)s * BTILE + bRowO;
        const uint32_t aB  = aBase + (uint32_t)s * ATILE;
#pragma unroll
        for (int ks = 0; ks < 4; ks++) {
            const uint32_t kb = (uint32_t)ks << 5;
            uint32_t ah[8], bh[16];
            ldsm4(ah,     aB + kb);
            ldsm4(ah + 4, aB + 16 * BROW + kb);
#pragma unroll
            for (int j = 0; j < 4; j++) ldsm4(bh + j * 4, bHi + (uint32_t)j * 16 * BROW + kb);
            mma_all(acc, ah, bh);
        }

        // ---- descriptors for the tap after next (double-buffered) ----
        if ((k + 2) < NCHUNK && (((k + 2) & 3) == 0))
            desc_gen((k + 2) >> 2, ((k + 2) >> 2) & 1);

        // ---- A-gen(k+1) overlapped with MMA pipe drain ----
        if (k + 1 < NCHUNK) {
            a_gen(k + 1, (k + 1) & 1, ((k + 1) >> 2) & 1);
            asm volatile("cp.async.wait_group 0;" ::: "memory");
        }
        __syncthreads();
    }

    // ---- Epilogue: direct stores (sector-dense: 8 consecutive m per o) ----
    const int g  = lane >> 2;
    const int tt = lane & 3;
#pragma unroll
    for (int mt = 0; mt < 2; mt++) {
        const int m = wm * 32 + mt * 16 + g;
        float* pm = out + hwb + m;
#pragma unroll
        for (int nn = 0; nn < 8; nn++) {
            const int o = wn * 64 + nn * 8 + tt * 2;
            float* p = pm + ((size_t)(nb * O_OUT + o) << 12);
            p[0]        = acc[mt][nn][0];
            p[4096]     = acc[mt][nn][1];
            p[8]        = acc[mt][nn][2];
            p[4096 + 8] = acc[mt][nn][3];
        }
    }
}

// ---------------------------------------------------------------------------
extern "C" void kernel_launch(void* const* d_in, const int* in_sizes, int n_in,
                              void* d_out, int out_size) {
    (void)out_size;
    const float* x = nullptr;
    const float* offset = nullptr;
    const float* weight = nullptr;
    for (int i = 0; i < n_in; i++) {
        const int sz = in_sizes[i];
        if (sz == NB * C_IN * HH * WW)    x = (const float*)d_in[i];
        else if (sz == NB * HH * WW * 18) offset = (const float*)d_in[i];
        else if (sz == O_OUT * C_IN * 9)  weight = (const float*)d_in[i];
    }
    float* out = (float*)d_out;

    cudaFuncSetAttribute(deform_mma_kernel, cudaFuncAttributeMaxDynamicSharedMemorySize, SMEM_BYTES);

    transpose_x_kernel<<<dim3(16, NB * HH), 256>>>(x);
    prep_w_kernel<<<(NCHUNK * 8192 + 255) / 256, 256>>>(weight);
    deform_mma_kernel<<<128, 512, SMEM_BYTES>>>(offset, out);
}

// round 13
// speedup vs baseline: 6.6335x; 1.0054x over previous
#include <cuda_runtime.h>
#include <cuda_fp16.h>
#include <math.h>
#include <stdint.h>

// Problem constants
#define NB    4
#define HH    64
#define WW    64
#define C_IN  256
#define O_OUT 256
#define NCHUNK 36            // 9 taps * 4 channel-blocks of 64
// GEMM: M=16384 (positions), N=256 (outputs), K=2304 (tap-major)

// Tiles: rows padded to 144B (9 x 16B) for conflict-free ldmatrix/STS
#define BROW    144
#define BTILE   36864        // 256 o x 144 B (single fp16 B tile per chunk)
#define ATILE   18432        // 128 m x 144 B (single fp16 A tile)

// Scratch (__device__ globals per allocation-free rule)
__device__ __half g_xTh[(size_t)NB * HH * WW * C_IN];               // [n][h][w][c] fp16
__device__ __align__(128) unsigned char g_wB[(size_t)NCHUNK * BTILE];

// ---------------- PTX helpers (non-'a' features only) ----------------
__device__ __forceinline__ uint32_t smem_u32(const void* p) {
    uint32_t a;
    asm("{ .reg .u64 t; cvta.to.shared.u64 t, %1; cvt.u32.u64 %0, t; }" : "=r"(a) : "l"(p));
    return a;
}
__device__ __forceinline__ void ldsm4(uint32_t* r, uint32_t addr) {
    asm volatile("ldmatrix.sync.aligned.m8n8.x4.shared.b16 {%0,%1,%2,%3}, [%4];"
        : "=r"(r[0]), "=r"(r[1]), "=r"(r[2]), "=r"(r[3]) : "r"(addr));
}
__device__ __forceinline__ void cpasync16(uint32_t dst, const void* src) {
    asm volatile("cp.async.cg.shared.global [%0], [%1], 16;" :: "r"(dst), "l"(src) : "memory");
}
__device__ __forceinline__ void sts128(uint32_t addr, uint32_t a, uint32_t b, uint32_t c, uint32_t d) {
    asm volatile("st.shared.v4.b32 [%0], {%1, %2, %3, %4};" :: "r"(addr), "r"(a), "r"(b), "r"(c), "r"(d) : "memory");
}
__device__ __forceinline__ uint32_t packh(float lo, float hi) {
    uint32_t r; asm("cvt.rn.f16x2.f32 %0, %1, %2;" : "=r"(r) : "f"(hi), "f"(lo)); return r;  // low16 = lo
}
// 16 warp-MMAs: full 32(M) x 64(N) warp tile, one k16 step (fp16 in, fp32 acc)
__device__ __forceinline__ void mma_all(float (&acc)[2][8][4], const uint32_t* a, const uint32_t* b) {
#pragma unroll
    for (int mt = 0; mt < 2; mt++)
#pragma unroll
        for (int nn = 0; nn < 8; nn++) {
            const uint32_t* bb = b + (nn >> 1) * 4 + (nn & 1) * 2;
            asm volatile("mma.sync.aligned.m16n8k16.row.col.f32.f16.f16.f32 "
                "{%0,%1,%2,%3}, {%4,%5,%6,%7}, {%8,%9}, {%0,%1,%2,%3};"
                : "+f"(acc[mt][nn][0]), "+f"(acc[mt][nn][1]), "+f"(acc[mt][nn][2]), "+f"(acc[mt][nn][3])
                : "r"(a[mt * 4]), "r"(a[mt * 4 + 1]), "r"(a[mt * 4 + 2]), "r"(a[mt * 4 + 3]),
                  "r"(bb[0]), "r"(bb[1]));
        }
}

// -------- smem layout (dynamic) --------
#define SM_ADDR   64        // int   [2 dstage][4 corner][128]  = 4096 B
#define SM_WGT    4160      // float [2 dstage][4 corner][128]  = 4096 B
#define SM_A      8320      // 2 stages x 18432
#define SM_B      45184     // 2 stages x 36864
#define SMEM_BYTES 118912

// ---------------------------------------------------------------------------
// x: [N,C,H,W] fp32 -> [N,H,W,C] fp16
// 64c x 64w tile per block; 16 independent LDGs/thread (deep MLP);
// smem stride 66 floats -> conflict-free on both sides; half2 (dense) writes.
// grid (4 c-tiles, 256 nh), 256 threads.
// ---------------------------------------------------------------------------
__global__ __launch_bounds__(256)
void transpose_x_kernel(const float* __restrict__ x) {
    __shared__ float tile[64][66];
    const int nh = blockIdx.y;            // n*64 + h
    const int c0 = blockIdx.x << 6;       // 0,64,128,192
    const int t  = threadIdx.x;
    const int n  = nh >> 6;
    const int h  = nh & 63;

    const float* xp = x + ((size_t)n * C_IN + c0) * (HH * WW) + h * WW;
    const int wl = t & 31;                // lane -> w
    const int wr = t >> 5;                // warp -> c row group
#pragma unroll
    for (int r = 0; r < 8; r++) {
        const int c = wr + r * 8;
        tile[c][wl]      = xp[(size_t)c * (HH * WW) + wl];
        tile[c][wl + 32] = xp[(size_t)c * (HH * WW) + wl + 32];
    }
    __syncthreads();

    __half2* op = (__half2*)(g_xTh + ((size_t)nh * WW) * C_IN + c0);
    const int j     = t & 7;
    const int wbase = t >> 3;             // 0..31
#pragma unroll
    for (int p = 0; p < 2; p++) {
        const int w = p * 32 + wbase;
#pragma unroll
        for (int i = 0; i < 4; i++) {
            const int cp = j + 8 * i;     // half2 index within 64 channels
            op[(size_t)w * (C_IN / 2) + cp] =
                __floats2half2_rn(tile[2 * cp][w], tile[2 * cp + 1][w]);
        }
    }
}

// ---------------------------------------------------------------------------
// weight [O,C,3,3] fp32 -> fp16 padded-row B tiles per chunk
// ---------------------------------------------------------------------------
__global__ void prep_w_kernel(const float* __restrict__ w) {
    int idx = blockIdx.x * 256 + threadIdx.x;          // 0 .. 36*8192-1
    if (idx >= NCHUNK * 8192) return;
    const int chunk = idx >> 13;
    const int r  = idx & 8191;
    const int o  = r >> 5;          // 0..255
    const int j2 = r & 31;          // fp16-pair index within 64-ch row
    const int tap = chunk >> 2, cb = chunk & 3;
    const int c = cb * 64 + 2 * j2;
    const float v0 = w[(o * C_IN + c) * 9 + tap];
    const float v1 = w[(o * C_IN + c + 1) * 9 + tap];
    __half2 h = __floats2half2_rn(v0, v1);
    *(uint32_t*)(g_wB + (size_t)chunk * BTILE + (size_t)o * BROW + j2 * 4) = *(uint32_t*)&h;
}

// ---------------------------------------------------------------------------
// Fused bilinear-im2col + fp16 mma.sync GEMM (single product).
// grid = 128 CTAs (4 n x 32 tiles of 128 positions), 512 threads, 1 CTA/SM.
// Warp layout: 16 warps = 4(M blocks of 32) x 4(N blocks of 64).
// A-gen lane map: (pos = t>>2, cg = t&3) so the 4 lanes of one position hit
// ONE 128B line per corner load (8 wavefronts/instr instead of 32).
// ---------------------------------------------------------------------------
__global__ __launch_bounds__(512, 1)
void deform_mma_kernel(const float* __restrict__ offset, float* __restrict__ out) {
    extern __shared__ char smem[];
    const uint32_t sb = smem_u32(smem);
    const int t    = threadIdx.x;
    const int blk  = blockIdx.x;           // 0..127
    const int nb   = blk >> 5;
    const int hwb  = (blk & 31) * 128;
    const int warp = t >> 5, lane = t & 31;
    const int wm = warp & 3, wn = warp >> 2;

    int*   s_addr = (int*)(smem + SM_ADDR);    // [dstage][corner][128]
    float* s_wgt  = (float*)(smem + SM_WGT);

    float acc[2][8][4];
#pragma unroll
    for (int mt = 0; mt < 2; mt++)
#pragma unroll
        for (int nn = 0; nn < 8; nn++)
#pragma unroll
            for (int q = 0; q < 4; q++) acc[mt][nn][q] = 0.f;

    // per-thread constant addressing
    const int pos = t >> 2;         // A-gen: position (0..127)
    const int cg  = t & 3;          // A-gen: 16-channel group (0..3)
    const uint32_t aGenB = sb + SM_A + pos * BROW + cg * 32;
    const uint32_t aBase = sb + SM_A + (wm * 32 + (lane & 15)) * BROW + ((lane >> 4) << 4);
    const uint32_t bRowO = (uint32_t)(wn * 64 + (lane & 7) + ((lane >> 4) << 3)) * BROW
                         + (((lane >> 3) & 1) << 4);

    // ---- descriptor generator (bilinear corners for one tap) ----
    auto desc_gen = [&](int tap, int ds) {
        if (t < 128) {
            const int p  = t;
            const int hw = hwb + p;
            const int h  = hw >> 6, w = hw & 63;
            const float2 dydx = *(const float2*)(offset + ((size_t)(nb * 4096 + hw)) * 18 + 2 * tap);
            const float py = (float)(h + (tap / 3) - 1) + dydx.x;
            const float px = (float)(w + (tap % 3) - 1) + dydx.y;
            const float fy = floorf(py), fx = floorf(px);
            const float wy = py - fy, wx = px - fx;
            const int iy0 = (int)fy, ix0 = (int)fx;
            const float cw[4] = {(1.f - wy) * (1.f - wx), (1.f - wy) * wx, wy * (1.f - wx), wy * wx};
#pragma unroll
            for (int q = 0; q < 4; q++) {
                const int iy = iy0 + (q >> 1);
                const int ix = ix0 + (q & 1);
                const bool valid = (iy >= 0) && (iy < HH) && (ix >= 0) && (ix < WW);
                const int iyc = min(max(iy, 0), HH - 1);
                const int ixc = min(max(ix, 0), WW - 1);
                s_addr[(ds * 4 + q) * 128 + p] = ((nb * HH + iyc) * WW + ixc) * C_IN;
                s_wgt[(ds * 4 + q) * 128 + p]  = valid ? cw[q] : 0.f;
            }
        }
    };

    // ---- A-tile generator: this thread = (pos, 16 channels), fp16 in/out ----
    auto a_gen = [&](int chunk, int as, int ds) {
        const int cb = chunk & 3;
        const int c0 = cb * 64 + cg * 16;
        const int base = ds * 4 * 128 + pos;
        const int a0 = s_addr[base]       + c0;
        const int a1 = s_addr[base + 128] + c0;
        const int a2 = s_addr[base + 256] + c0;
        const int a3 = s_addr[base + 384] + c0;
        const float q0 = s_wgt[base],       q1 = s_wgt[base + 128];
        const float q2 = s_wgt[base + 256], q3 = s_wgt[base + 384];
        // 16 channels = 2 x uint4 (8 half2) per corner; 4 lanes of one pos
        // cover one 128B line per instruction.
        uint4 u0a = *(const uint4*)(g_xTh + a0);
        uint4 u0b = *(const uint4*)(g_xTh + a0 + 8);
        uint4 u1a = *(const uint4*)(g_xTh + a1);
        uint4 u1b = *(const uint4*)(g_xTh + a1 + 8);
        uint4 u2a = *(const uint4*)(g_xTh + a2);
        uint4 u2b = *(const uint4*)(g_xTh + a2 + 8);
        uint4 u3a = *(const uint4*)(g_xTh + a3);
        uint4 u3b = *(const uint4*)(g_xTh + a3 + 8);
        const uint32_t* p0 = (const uint32_t*)&u0a;
        const uint32_t* p1 = (const uint32_t*)&u1a;
        const uint32_t* p2 = (const uint32_t*)&u2a;
        const uint32_t* p3 = (const uint32_t*)&u3a;
        uint32_t o[8];
#pragma unroll
        for (int j = 0; j < 8; j++) {
            const uint32_t w0 = (j < 4) ? p0[j] : ((const uint32_t*)&u0b)[j - 4];
            const uint32_t w1 = (j < 4) ? p1[j] : ((const uint32_t*)&u1b)[j - 4];
            const uint32_t w2 = (j < 4) ? p2[j] : ((const uint32_t*)&u2b)[j - 4];
            const uint32_t w3 = (j < 4) ? p3[j] : ((const uint32_t*)&u3b)[j - 4];
            const float2 f0 = __half22float2(*(const __half2*)&w0);
            const float2 f1 = __half22float2(*(const __half2*)&w1);
            const float2 f2 = __half22float2(*(const __half2*)&w2);
            const float2 f3 = __half22float2(*(const __half2*)&w3);
            const float vx = q0 * f0.x + q1 * f1.x + q2 * f2.x + q3 * f3.x;
            const float vy = q0 * f0.y + q1 * f1.y + q2 * f2.y + q3 * f3.y;
            o[j] = packh(vx, vy);
        }
        const uint32_t dst = aGenB + (uint32_t)as * ATILE;
        sts128(dst,      o[0], o[1], o[2], o[3]);
        sts128(dst + 16, o[4], o[5], o[6], o[7]);
    };

    // ---- B prefetch: 36864 B per chunk ----
    auto b_fetch = [&](int chunk) {
        const uint32_t dst = sb + SM_B + (uint32_t)(chunk & 1) * BTILE;
        const unsigned char* src = g_wB + (size_t)chunk * BTILE;
#pragma unroll
        for (int i = 0; i < 4; i++) {
            const int off = (t + i * 512) * 16;
            cpasync16(dst + off, src + off);
        }
        if (t < 256) {
            const int off = (t + 2048) * 16;
            cpasync16(dst + off, src + off);
        }
        asm volatile("cp.async.commit_group;" ::: "memory");
    };

    // ================= prologue =================
    desc_gen(0, 0);
    b_fetch(0);
    __syncthreads();                 // desc(0) visible
    a_gen(0, 0, 0);
    asm volatile("cp.async.wait_group 0;" ::: "memory");
    __syncthreads();                 // A(0), B(0) ready

    // ================= main loop =================
    for (int k = 0; k < NCHUNK; k++) {
        const int s = k & 1;
        if (k + 1 < NCHUNK) b_fetch(k + 1);

        // ---- MMA(k): 4 k16 steps, single fp16 product ----
        const uint32_t bHi = sb + SM_B + (uint32_t)s * BTILE + bRowO;
        const uint32_t aB  = aBase + (uint32_t)s * ATILE;
#pragma unroll
        for (int ks = 0; ks < 4; ks++) {
            const uint32_t kb = (uint32_t)ks << 5;
            uint32_t ah[8], bh[16];
            ldsm4(ah,     aB + kb);
            ldsm4(ah + 4, aB + 16 * BROW + kb);
#pragma unroll
            for (int j = 0; j < 4; j++) ldsm4(bh + j * 4, bHi + (uint32_t)j * 16 * BROW + kb);
            mma_all(acc, ah, bh);
        }

        // ---- descriptors for the tap after next (double-buffered) ----
        if ((k + 2) < NCHUNK && (((k + 2) & 3) == 0))
            desc_gen((k + 2) >> 2, ((k + 2) >> 2) & 1);

        // ---- A-gen(k+1) overlapped with MMA pipe drain ----
        if (k + 1 < NCHUNK) {
            a_gen(k + 1, (k + 1) & 1, ((k + 1) >> 2) & 1);
            asm volatile("cp.async.wait_group 0;" ::: "memory");
        }
        __syncthreads();
    }

    // ---- Epilogue: direct stores (sector-dense: 8 consecutive m per o) ----
    const int g  = lane >> 2;
    const int tt = lane & 3;
#pragma unroll
    for (int mt = 0; mt < 2; mt++) {
        const int m = wm * 32 + mt * 16 + g;
        float* pm = out + hwb + m;
#pragma unroll
        for (int nn = 0; nn < 8; nn++) {
            const int o = wn * 64 + nn * 8 + tt * 2;
            float* p = pm + ((size_t)(nb * O_OUT + o) << 12);
            p[0]        = acc[mt][nn][0];
            p[4096]     = acc[mt][nn][1];
            p[8]        = acc[mt][nn][2];
            p[4096 + 8] = acc[mt][nn][3];
        }
    }
}

// ---------------------------------------------------------------------------
extern "C" void kernel_launch(void* const* d_in, const int* in_sizes, int n_in,
                              void* d_out, int out_size) {
    (void)out_size;
    const float* x = nullptr;
    const float* offset = nullptr;
    const float* weight = nullptr;
    for (int i = 0; i < n_in; i++) {
        const int sz = in_sizes[i];
        if (sz == NB * C_IN * HH * WW)    x = (const float*)d_in[i];
        else if (sz == NB * HH * WW * 18) offset = (const float*)d_in[i];
        else if (sz == O_OUT * C_IN * 9)  weight = (const float*)d_in[i];
    }
    float* out = (float*)d_out;

    cudaFuncSetAttribute(deform_mma_kernel, cudaFuncAttributeMaxDynamicSharedMemorySize, SMEM_BYTES);

    transpose_x_kernel<<<dim3(4, NB * HH), 256>>>(x);
    prep_w_kernel<<<(NCHUNK * 8192 + 255) / 256, 256>>>(weight);
    deform_mma_kernel<<<128, 512, SMEM_BYTES>>>(offset, out);
}

// round 15
// speedup vs baseline: 6.6504x; 1.0025x over previous
#include <cuda_runtime.h>
#include <cuda_fp16.h>
#include <math.h>
#include <stdint.h>

// Problem constants
#define NB    4
#define HH    64
#define WW    64
#define C_IN  256
#define O_OUT 256
#define NCHUNK 36            // 9 taps * 4 channel-blocks of 64
// GEMM: M=16384 (positions), N=256 (outputs), K=2304 (tap-major)

// Tiles: rows padded to 144B (9 x 16B) for conflict-free ldmatrix/STS
#define BROW    144
#define BTILE   36864        // 256 o x 144 B (single fp16 B tile per chunk)
#define ATILE   18432        // 128 m x 144 B (single fp16 A tile)

// Scratch (__device__ globals per allocation-free rule)
__device__ __half g_xTh[(size_t)NB * HH * WW * C_IN];               // [n][h][w][c] fp16
__device__ __align__(128) unsigned char g_wB[(size_t)NCHUNK * BTILE];

// ---------------- PTX helpers (non-'a' features only) ----------------
__device__ __forceinline__ uint32_t smem_u32(const void* p) {
    uint32_t a;
    asm("{ .reg .u64 t; cvta.to.shared.u64 t, %1; cvt.u32.u64 %0, t; }" : "=r"(a) : "l"(p));
    return a;
}
__device__ __forceinline__ void ldsm4(uint32_t* r, uint32_t addr) {
    asm volatile("ldmatrix.sync.aligned.m8n8.x4.shared.b16 {%0,%1,%2,%3}, [%4];"
        : "=r"(r[0]), "=r"(r[1]), "=r"(r[2]), "=r"(r[3]) : "r"(addr));
}
__device__ __forceinline__ void cpasync16(uint32_t dst, const void* src) {
    asm volatile("cp.async.cg.shared.global [%0], [%1], 16;" :: "r"(dst), "l"(src) : "memory");
}
__device__ __forceinline__ void sts128(uint32_t addr, uint32_t a, uint32_t b, uint32_t c, uint32_t d) {
    asm volatile("st.shared.v4.b32 [%0], {%1, %2, %3, %4};" :: "r"(addr), "r"(a), "r"(b), "r"(c), "r"(d) : "memory");
}
__device__ __forceinline__ uint32_t packh(float lo, float hi) {
    uint32_t r; asm("cvt.rn.f16x2.f32 %0, %1, %2;" : "=r"(r) : "f"(hi), "f"(lo)); return r;  // low16 = lo
}
// 16 warp-MMAs: full 32(M) x 64(N) warp tile, one k16 step (fp16 in, fp32 acc)
__device__ __forceinline__ void mma_all(float (&acc)[2][8][4], const uint32_t* a, const uint32_t* b) {
#pragma unroll
    for (int mt = 0; mt < 2; mt++)
#pragma unroll
        for (int nn = 0; nn < 8; nn++) {
            const uint32_t* bb = b + (nn >> 1) * 4 + (nn & 1) * 2;
            asm volatile("mma.sync.aligned.m16n8k16.row.col.f32.f16.f16.f32 "
                "{%0,%1,%2,%3}, {%4,%5,%6,%7}, {%8,%9}, {%0,%1,%2,%3};"
                : "+f"(acc[mt][nn][0]), "+f"(acc[mt][nn][1]), "+f"(acc[mt][nn][2]), "+f"(acc[mt][nn][3])
                : "r"(a[mt * 4]), "r"(a[mt * 4 + 1]), "r"(a[mt * 4 + 2]), "r"(a[mt * 4 + 3]),
                  "r"(bb[0]), "r"(bb[1]));
        }
}

// -------- smem layout (dynamic, main kernel) --------
#define SM_ADDR   64        // int   [2 dstage][4 corner][128]  = 4096 B
#define SM_WGT    4160      // float [2 dstage][4 corner][128]  = 4096 B
#define SM_A      8320      // 2 stages x 18432
#define SM_B      45184     // 2 stages x 36864
#define SMEM_BYTES 118912

// ---------------------------------------------------------------------------
// Fused prep: blocks [0,1024) transpose x fp32 NCHW -> fp16 NHWC;
//             blocks [1024,2176) convert weight -> fp16 padded B tiles.
// One launch: prep_w rides inside the transpose's latency shadow.
// ---------------------------------------------------------------------------
__global__ __launch_bounds__(256)
void prep_kernel(const float* __restrict__ x, const float* __restrict__ w) {
    if (blockIdx.x < 1024) {
        // ---- transpose: 64c x 64w tile, smem [w][c] stride 65 ----
        __shared__ float tile[64][65];
        const int bx = blockIdx.x;
        const int nh = bx >> 2;               // n*64 + h
        const int c0 = (bx & 3) << 6;         // 0,64,128,192
        const int t  = threadIdx.x;
        const int n  = nh >> 6;
        const int h  = nh & 63;

        const float* xp = x + ((size_t)n * C_IN + c0) * (HH * WW) + h * WW;
        const int warp  = t >> 5, lane = t & 31;
        const int rhalf = lane >> 4;          // row within pair
        const int l4    = (lane & 15) << 2;   // w offset (float4)
#pragma unroll
        for (int r = 0; r < 4; r++) {
            const int c = warp * 8 + r * 2 + rhalf;
            const float4 v = *(const float4*)(xp + (size_t)c * (HH * WW) + l4);
            tile[l4][c]     = v.x;
            tile[l4 + 1][c] = v.y;
            tile[l4 + 2][c] = v.z;
            tile[l4 + 3][c] = v.w;
        }
        __syncthreads();

        const int j  = t & 7;                 // 8-channel group
        const int w2 = t >> 3;                // 0..31
        __half* ob = g_xTh + (size_t)nh * (WW * C_IN) + c0 + 8 * j;
#pragma unroll
        for (int p = 0; p < 2; p++) {
            const int ww = p * 32 + w2;
            const float* tr = &tile[ww][8 * j];
            __half2 h0 = __floats2half2_rn(tr[0], tr[1]);
            __half2 h1 = __floats2half2_rn(tr[2], tr[3]);
            __half2 h2 = __floats2half2_rn(tr[4], tr[5]);
            __half2 h3 = __floats2half2_rn(tr[6], tr[7]);
            uint4 u;
            u.x = *(uint32_t*)&h0; u.y = *(uint32_t*)&h1;
            u.z = *(uint32_t*)&h2; u.w = *(uint32_t*)&h3;
            *(uint4*)(ob + (size_t)ww * C_IN) = u;
        }
    } else {
        // ---- weight [O,C,3,3] fp32 -> fp16 padded-row B tiles ----
        int idx = (blockIdx.x - 1024) * 256 + threadIdx.x;   // 0 .. 36*8192-1
        if (idx >= NCHUNK * 8192) return;
        const int chunk = idx >> 13;
        const int r  = idx & 8191;
        const int o  = r >> 5;          // 0..255
        const int j2 = r & 31;          // fp16-pair index within 64-ch row
        const int tap = chunk >> 2, cb = chunk & 3;
        const int c = cb * 64 + 2 * j2;
        const float v0 = w[(o * C_IN + c) * 9 + tap];
        const float v1 = w[(o * C_IN + c + 1) * 9 + tap];
        __half2 h = __floats2half2_rn(v0, v1);
        *(uint32_t*)(g_wB + (size_t)chunk * BTILE + (size_t)o * BROW + j2 * 4) = *(uint32_t*)&h;
    }
}

// ---------------------------------------------------------------------------
// Fused bilinear-im2col + fp16 mma.sync GEMM (single product).
// grid = 128 CTAs (4 n x 32 tiles of 128 positions), 512 threads, 1 CTA/SM.
// Warp layout: 16 warps = 4(M blocks of 32) x 4(N blocks of 64).
// A-gen lane map: (pos = t>>2, cg = t&3) so the 4 lanes of one position hit
// ONE 128B line per corner load (8 wavefronts/instr instead of 32).
// ---------------------------------------------------------------------------
__global__ __launch_bounds__(512, 1)
void deform_mma_kernel(const float* __restrict__ offset, float* __restrict__ out) {
    extern __shared__ char smem[];
    const uint32_t sb = smem_u32(smem);
    const int t    = threadIdx.x;
    const int blk  = blockIdx.x;           // 0..127
    const int nb   = blk >> 5;
    const int hwb  = (blk & 31) * 128;
    const int warp = t >> 5, lane = t & 31;
    const int wm = warp & 3, wn = warp >> 2;

    int*   s_addr = (int*)(smem + SM_ADDR);    // [dstage][corner][128]
    float* s_wgt  = (float*)(smem + SM_WGT);

    float acc[2][8][4];
#pragma unroll
    for (int mt = 0; mt < 2; mt++)
#pragma unroll
        for (int nn = 0; nn < 8; nn++)
#pragma unroll
            for (int q = 0; q < 4; q++) acc[mt][nn][q] = 0.f;

    // per-thread constant addressing
    const int pos = t >> 2;         // A-gen: position (0..127)
    const int cg  = t & 3;          // A-gen: 16-channel group (0..3)
    const uint32_t aGenB = sb + SM_A + pos * BROW + cg * 32;
    const uint32_t aBase = sb + SM_A + (wm * 32 + (lane & 15)) * BROW + ((lane >> 4) << 4);
    const uint32_t bRowO = (uint32_t)(wn * 64 + (lane & 7) + ((lane >> 4) << 3)) * BROW
                         + (((lane >> 3) & 1) << 4);

    // ---- descriptor generator (bilinear corners for one tap) ----
    auto desc_gen = [&](int tap, int ds) {
        if (t < 128) {
            const int p  = t;
            const int hw = hwb + p;
            const int h  = hw >> 6, w = hw & 63;
            const float2 dydx = *(const float2*)(offset + ((size_t)(nb * 4096 + hw)) * 18 + 2 * tap);
            const float py = (float)(h + (tap / 3) - 1) + dydx.x;
            const float px = (float)(w + (tap % 3) - 1) + dydx.y;
            const float fy = floorf(py), fx = floorf(px);
            const float wy = py - fy, wx = px - fx;
            const int iy0 = (int)fy, ix0 = (int)fx;
            const float cw[4] = {(1.f - wy) * (1.f - wx), (1.f - wy) * wx, wy * (1.f - wx), wy * wx};
#pragma unroll
            for (int q = 0; q < 4; q++) {
                const int iy = iy0 + (q >> 1);
                const int ix = ix0 + (q & 1);
                const bool valid = (iy >= 0) && (iy < HH) && (ix >= 0) && (ix < WW);
                const int iyc = min(max(iy, 0), HH - 1);
                const int ixc = min(max(ix, 0), WW - 1);
                s_addr[(ds * 4 + q) * 128 + p] = ((nb * HH + iyc) * WW + ixc) * C_IN;
                s_wgt[(ds * 4 + q) * 128 + p]  = valid ? cw[q] : 0.f;
            }
        }
    };

    // ---- A-tile generator: this thread = (pos, 16 channels), fp16 in/out ----
    auto a_gen = [&](int chunk, int as, int ds) {
        const int cb = chunk & 3;
        const int c0 = cb * 64 + cg * 16;
        const int base = ds * 4 * 128 + pos;
        const int a0 = s_addr[base]       + c0;
        const int a1 = s_addr[base + 128] + c0;
        const int a2 = s_addr[base + 256] + c0;
        const int a3 = s_addr[base + 384] + c0;
        const float q0 = s_wgt[base],       q1 = s_wgt[base + 128];
        const float q2 = s_wgt[base + 256], q3 = s_wgt[base + 384];
        // 16 channels = 2 x uint4 (8 half2) per corner; 4 lanes of one pos
        // cover one 128B line per instruction.
        uint4 u0a = *(const uint4*)(g_xTh + a0);
        uint4 u0b = *(const uint4*)(g_xTh + a0 + 8);
        uint4 u1a = *(const uint4*)(g_xTh + a1);
        uint4 u1b = *(const uint4*)(g_xTh + a1 + 8);
        uint4 u2a = *(const uint4*)(g_xTh + a2);
        uint4 u2b = *(const uint4*)(g_xTh + a2 + 8);
        uint4 u3a = *(const uint4*)(g_xTh + a3);
        uint4 u3b = *(const uint4*)(g_xTh + a3 + 8);
        const uint32_t* p0 = (const uint32_t*)&u0a;
        const uint32_t* p1 = (const uint32_t*)&u1a;
        const uint32_t* p2 = (const uint32_t*)&u2a;
        const uint32_t* p3 = (const uint32_t*)&u3a;
        uint32_t o[8];
#pragma unroll
        for (int j = 0; j < 8; j++) {
            const uint32_t w0 = (j < 4) ? p0[j] : ((const uint32_t*)&u0b)[j - 4];
            const uint32_t w1 = (j < 4) ? p1[j] : ((const uint32_t*)&u1b)[j - 4];
            const uint32_t w2 = (j < 4) ? p2[j] : ((const uint32_t*)&u2b)[j - 4];
            const uint32_t w3 = (j < 4) ? p3[j] : ((const uint32_t*)&u3b)[j - 4];
            const float2 f0 = __half22float2(*(const __half2*)&w0);
            const float2 f1 = __half22float2(*(const __half2*)&w1);
            const float2 f2 = __half22float2(*(const __half2*)&w2);
            const float2 f3 = __half22float2(*(const __half2*)&w3);
            const float vx = q0 * f0.x + q1 * f1.x + q2 * f2.x + q3 * f3.x;
            const float vy = q0 * f0.y + q1 * f1.y + q2 * f2.y + q3 * f3.y;
            o[j] = packh(vx, vy);
        }
        const uint32_t dst = aGenB + (uint32_t)as * ATILE;
        sts128(dst,      o[0], o[1], o[2], o[3]);
        sts128(dst + 16, o[4], o[5], o[6], o[7]);
    };

    // ---- B prefetch: 36864 B per chunk ----
    auto b_fetch = [&](int chunk) {
        const uint32_t dst = sb + SM_B + (uint32_t)(chunk & 1) * BTILE;
        const unsigned char* src = g_wB + (size_t)chunk * BTILE;
#pragma unroll
        for (int i = 0; i < 4; i++) {
            const int off = (t + i * 512) * 16;
            cpasync16(dst + off, src + off);
        }
        if (t < 256) {
            const int off = (t + 2048) * 16;
            cpasync16(dst + off, src + off);
        }
        asm volatile("cp.async.commit_group;" ::: "memory");
    };

    // ================= prologue =================
    desc_gen(0, 0);
    b_fetch(0);
    __syncthreads();                 // desc(0) visible
    a_gen(0, 0, 0);
    asm volatile("cp.async.wait_group 0;" ::: "memory");
    __syncthreads();                 // A(0), B(0) ready

    // ================= main loop =================
    for (int k = 0; k < NCHUNK; k++) {
        const int s = k & 1;
        if (k + 1 < NCHUNK) b_fetch(k + 1);

        // ---- MMA(k): 4 k16 steps, single fp16 product ----
        const uint32_t bHi = sb + SM_B + (uint32_t)s * BTILE + bRowO;
        const uint32_t aB  = aBase + (uint32_t)s * ATILE;
#pragma unroll
        for (int ks = 0; ks < 4; ks++) {
            const uint32_t kb = (uint32_t)ks << 5;
            uint32_t ah[8], bh[16];
            ldsm4(ah,     aB + kb);
            ldsm4(ah + 4, aB + 16 * BROW + kb);
#pragma unroll
            for (int j = 0; j < 4; j++) ldsm4(bh + j * 4, bHi + (uint32_t)j * 16 * BROW + kb);
            mma_all(acc, ah, bh);
        }

        // ---- descriptors for the tap after next (double-buffered) ----
        if ((k + 2) < NCHUNK && (((k + 2) & 3) == 0))
            desc_gen((k + 2) >> 2, ((k + 2) >> 2) & 1);

        // ---- A-gen(k+1) overlapped with MMA pipe drain ----
        if (k + 1 < NCHUNK) {
            a_gen(k + 1, (k + 1) & 1, ((k + 1) >> 2) & 1);
            asm volatile("cp.async.wait_group 0;" ::: "memory");
        }
        __syncthreads();
    }

    // ---- Epilogue: direct stores (sector-dense: 8 consecutive m per o) ----
    const int g  = lane >> 2;
    const int tt = lane & 3;
#pragma unroll
    for (int mt = 0; mt < 2; mt++) {
        const int m = wm * 32 + mt * 16 + g;
        float* pm = out + hwb + m;
#pragma unroll
        for (int nn = 0; nn < 8; nn++) {
            const int o = wn * 64 + nn * 8 + tt * 2;
            float* p = pm + ((size_t)(nb * O_OUT + o) << 12);
            p[0]        = acc[mt][nn][0];
            p[4096]     = acc[mt][nn][1];
            p[8]        = acc[mt][nn][2];
            p[4096 + 8] = acc[mt][nn][3];
        }
    }
}

// ---------------------------------------------------------------------------
extern "C" void kernel_launch(void* const* d_in, const int* in_sizes, int n_in,
                              void* d_out, int out_size) {
    (void)out_size;
    const float* x = nullptr;
    const float* offset = nullptr;
    const float* weight = nullptr;
    for (int i = 0; i < n_in; i++) {
        const int sz = in_sizes[i];
        if (sz == NB * C_IN * HH * WW)    x = (const float*)d_in[i];
        else if (sz == NB * HH * WW * 18) offset = (const float*)d_in[i];
        else if (sz == O_OUT * C_IN * 9)  weight = (const float*)d_in[i];
    }
    float* out = (float*)d_out;

    cudaFuncSetAttribute(deform_mma_kernel, cudaFuncAttributeMaxDynamicSharedMemorySize, SMEM_BYTES);

    const int wblocks = (NCHUNK * 8192 + 255) / 256;   // 1152
    prep_kernel<<<1024 + wblocks, 256>>>(x, weight);
    deform_mma_kernel<<<128, 512, SMEM_BYTES>>>(offset, out);
}